// round 1
// baseline (speedup 1.0000x reference)
#include <cuda_runtime.h>
#include <math.h>

// Problem constants
constexpr int Bz = 8, Sq = 256, H = 768, Lr = 2, NE = 4, FF = 3072;
constexpr int NH = 12, HD = 64;
constexpr int T = Bz * Sq;          // 2048 tokens
constexpr float EPS = 1e-5f;

// GEMM tiling
constexpr int BM = 128, BN = 64, BK = 16, TM = 8, TN = 4;

// Scratch (static device allocations — allowed)
__device__ float g_H1[T * H];
__device__ float g_Qb[T * H];
__device__ float g_Kb[T * H];
__device__ float g_Vb[T * H];
__device__ float g_mid[(size_t)T * FF];
__device__ int   g_perm[T];
__device__ int   g_rank[T];
__device__ int   g_cnt[NE];
__device__ int   g_off[NE];

// ---------------------------------------------------------------- PE add
__global__ void k_add_pe(const float* __restrict__ xin, float* __restrict__ x) {
    int idx = blockIdx.x * blockDim.x + threadIdx.x;
    if (idx >= T * H) return;
    int d = idx % H;
    int s = (idx / H) % Sq;
    int i2 = d & ~1;
    float div = expf(-(float)i2 * (9.210340371976184f / (float)H)); // ln(10000)/H
    float ang = (float)s * div;
    float pe = (d & 1) ? cosf(ang) : sinf(ang);
    x[idx] = xin[idx] + pe;
}

// ---------------------------------------------------------------- routing
__global__ void k_route(const int* __restrict__ ntp) {
    __shared__ int scnt[NE];
    __shared__ int soff[NE];
    int tid = threadIdx.x;
    if (tid < NE) scnt[tid] = 0;
    __syncthreads();
    for (int t = tid; t < T; t += blockDim.x) {
        int e = ntp[t];
        g_rank[t] = atomicAdd(&scnt[e], 1);
    }
    __syncthreads();
    if (tid == 0) {
        int a = 0;
        for (int e = 0; e < NE; e++) {
            soff[e] = a; g_off[e] = a; g_cnt[e] = scnt[e]; a += scnt[e];
        }
    }
    __syncthreads();
    for (int t = tid; t < T; t += blockDim.x) {
        int e = ntp[t];
        g_perm[soff[e] + g_rank[t]] = t;
    }
}

// ---------------------------------------------------------------- layernorm
__device__ __forceinline__ float block_sum_768(float v) {
    __shared__ float red[8];
    int tid = threadIdx.x;
    #pragma unroll
    for (int o = 16; o; o >>= 1) v += __shfl_xor_sync(0xffffffffu, v, o);
    if ((tid & 31) == 0) red[tid >> 5] = v;
    __syncthreads();
    float t = 0.f;
    if (tid < 32) {
        t = (tid < 8) ? red[tid] : 0.f;
        #pragma unroll
        for (int o = 4; o; o >>= 1) t += __shfl_xor_sync(0xffffffffu, t, o);
        if (tid == 0) red[0] = t;
    }
    __syncthreads();
    float r = red[0];
    __syncthreads();
    return r;
}

__global__ __launch_bounds__(256) void k_ln(const float* __restrict__ x,
                                            const float* __restrict__ w,
                                            const float* __restrict__ b) {
    int row = blockIdx.x;
    int tid = threadIdx.x;
    const float* xr = x + (size_t)row * H;
    float v0 = xr[tid], v1 = xr[tid + 256], v2 = xr[tid + 512];
    float mu = block_sum_768(v0 + v1 + v2) * (1.0f / H);
    float d0 = v0 - mu, d1 = v1 - mu, d2 = v2 - mu;
    float var = block_sum_768(d0 * d0 + d1 * d1 + d2 * d2) * (1.0f / H);
    float rstd = rsqrtf(var + EPS);
    float* orow = g_H1 + (size_t)row * H;
    orow[tid]       = d0 * rstd * w[tid]       + b[tid];
    orow[tid + 256] = d1 * rstd * w[tid + 256] + b[tid + 256];
    orow[tid + 512] = d2 * rstd * w[tid + 512] + b[tid + 512];
}

// ---------------------------------------------------------------- QKV GEMM
// C[z] = g_H1 @ W[z] + bias[z],  M=T, N=H, K=H, z in {Q,K,V}
__global__ __launch_bounds__(256) void k_qkv(
    const float* __restrict__ Wq, const float* __restrict__ Wk, const float* __restrict__ Wv,
    const float* __restrict__ bq, const float* __restrict__ bk, const float* __restrict__ bv)
{
    const float* Bm; const float* bias; float* C;
    if (blockIdx.z == 0)      { Bm = Wq; bias = bq; C = g_Qb; }
    else if (blockIdx.z == 1) { Bm = Wk; bias = bk; C = g_Kb; }
    else                      { Bm = Wv; bias = bv; C = g_Vb; }

    __shared__ float As[BK][BM];
    __shared__ float Bs[BK][BN];
    int tid = threadIdx.x;
    int trow = tid >> 4, tcol = tid & 15;
    int m0 = blockIdx.y * BM, n0 = blockIdx.x * BN;

    int ar0 = tid >> 2, ar1 = ar0 + 64;
    int acv = (tid & 3) * 4;
    const float* Arow0 = g_H1 + (size_t)(m0 + ar0) * H;
    const float* Arow1 = g_H1 + (size_t)(m0 + ar1) * H;
    int blr = tid >> 4, blc = (tid & 15) * 4;

    float acc[TM][TN] = {};
    for (int kt = 0; kt < H; kt += BK) {
        float4 a0 = *(const float4*)(Arow0 + kt + acv);
        float4 a1 = *(const float4*)(Arow1 + kt + acv);
        float4 b4 = *(const float4*)(Bm + (size_t)(kt + blr) * H + n0 + blc);
        As[acv + 0][ar0] = a0.x; As[acv + 1][ar0] = a0.y; As[acv + 2][ar0] = a0.z; As[acv + 3][ar0] = a0.w;
        As[acv + 0][ar1] = a1.x; As[acv + 1][ar1] = a1.y; As[acv + 2][ar1] = a1.z; As[acv + 3][ar1] = a1.w;
        *(float4*)&Bs[blr][blc] = b4;
        __syncthreads();
        #pragma unroll
        for (int k = 0; k < BK; k++) {
            float a[TM], bb[TN];
            *(float4*)&a[0] = *(float4*)&As[k][trow * TM];
            *(float4*)&a[4] = *(float4*)&As[k][trow * TM + 4];
            *(float4*)&bb[0] = *(float4*)&Bs[k][tcol * TN];
            #pragma unroll
            for (int i = 0; i < TM; i++)
                #pragma unroll
                for (int j = 0; j < TN; j++)
                    acc[i][j] += a[i] * bb[j];
        }
        __syncthreads();
    }
    #pragma unroll
    for (int i = 0; i < TM; i++) {
        size_t r = (size_t)(m0 + trow * TM + i) * H + n0 + tcol * TN;
        #pragma unroll
        for (int j = 0; j < TN; j++)
            C[r + j] = acc[i][j] + bias[n0 + tcol * TN + j];
    }
}

// ---------------------------------------------------------------- attention
// block = (qtile 64, head, batch). smem: Qs[64][65], Ks[256][65] (reused as P[64][256]), Vs[256][65]
constexpr int ATTN_SMEM = (64 * 65 + 256 * 65 + 256 * 65) * 4;

__global__ __launch_bounds__(256) void k_attn(float* __restrict__ x) {
    extern __shared__ float sm[];
    float* Qs = sm;
    float* Ks = sm + 64 * 65;
    float* Vs = sm + 64 * 65 + 256 * 65;
    int qt = blockIdx.x, hd = blockIdx.y, b = blockIdx.z;
    int tid = threadIdx.x;
    int hoff = hd * HD;

    for (int v = tid; v < 64 * 16; v += 256) {
        int r = v >> 4, cv = (v & 15) * 4;
        float4 t4 = *(const float4*)(g_Qb + (size_t)(b * Sq + qt * 64 + r) * H + hoff + cv);
        Qs[r * 65 + cv + 0] = t4.x; Qs[r * 65 + cv + 1] = t4.y;
        Qs[r * 65 + cv + 2] = t4.z; Qs[r * 65 + cv + 3] = t4.w;
    }
    for (int v = tid; v < 256 * 16; v += 256) {
        int r = v >> 4, cv = (v & 15) * 4;
        float4 k4 = *(const float4*)(g_Kb + (size_t)(b * Sq + r) * H + hoff + cv);
        Ks[r * 65 + cv + 0] = k4.x; Ks[r * 65 + cv + 1] = k4.y;
        Ks[r * 65 + cv + 2] = k4.z; Ks[r * 65 + cv + 3] = k4.w;
        float4 v4 = *(const float4*)(g_Vb + (size_t)(b * Sq + r) * H + hoff + cv);
        Vs[r * 65 + cv + 0] = v4.x; Vs[r * 65 + cv + 1] = v4.y;
        Vs[r * 65 + cv + 2] = v4.z; Vs[r * 65 + cv + 3] = v4.w;
    }
    __syncthreads();

    int w = tid >> 5, tc = tid & 31;
    float sc[8][8];
    #pragma unroll
    for (int i = 0; i < 8; i++)
        #pragma unroll
        for (int j = 0; j < 8; j++) sc[i][j] = 0.f;

    #pragma unroll 4
    for (int d = 0; d < HD; d++) {
        float a[8], bb[8];
        #pragma unroll
        for (int i = 0; i < 8; i++) a[i] = Qs[(w * 8 + i) * 65 + d];
        #pragma unroll
        for (int j = 0; j < 8; j++) bb[j] = Ks[(tc + 32 * j) * 65 + d];
        #pragma unroll
        for (int i = 0; i < 8; i++)
            #pragma unroll
            for (int j = 0; j < 8; j++) sc[i][j] += a[i] * bb[j];
    }
    __syncthreads();   // everyone done reading Ks before we overwrite as P

    float* Ps = Ks;    // 64 x 256
    #pragma unroll
    for (int i = 0; i < 8; i++) {
        float m = -1e30f;
        #pragma unroll
        for (int j = 0; j < 8; j++) m = fmaxf(m, sc[i][j]);
        #pragma unroll
        for (int o = 16; o; o >>= 1) m = fmaxf(m, __shfl_xor_sync(0xffffffffu, m, o));
        float s = 0.f;
        #pragma unroll
        for (int j = 0; j < 8; j++) { sc[i][j] = expf(sc[i][j] - m); s += sc[i][j]; }
        #pragma unroll
        for (int o = 16; o; o >>= 1) s += __shfl_xor_sync(0xffffffffu, s, o);
        float inv = 1.f / s;
        #pragma unroll
        for (int j = 0; j < 8; j++)
            Ps[(w * 8 + i) * 256 + tc + 32 * j] = sc[i][j] * inv;
    }
    __syncthreads();

    int tr2 = tid >> 4, tc2 = tid & 15;
    float o[4][4] = {};
    #pragma unroll 4
    for (int kk = 0; kk < Sq; kk++) {
        float a[4], bb[4];
        #pragma unroll
        for (int i = 0; i < 4; i++) a[i] = Ps[(tr2 * 4 + i) * 256 + kk];
        #pragma unroll
        for (int j = 0; j < 4; j++) bb[j] = Vs[kk * 65 + tc2 * 4 + j];
        #pragma unroll
        for (int i = 0; i < 4; i++)
            #pragma unroll
            for (int j = 0; j < 4; j++) o[i][j] += a[i] * bb[j];
    }
    #pragma unroll
    for (int i = 0; i < 4; i++) {
        size_t r = (size_t)(b * Sq + qt * 64 + tr2 * 4 + i) * H + hoff + tc2 * 4;
        #pragma unroll
        for (int j = 0; j < 4; j++) x[r + j] += o[i][j];
    }
}

// ---------------------------------------------------------------- FFN GEMM1 (gather, gelu)
__global__ __launch_bounds__(256) void k_ffn1(const float* __restrict__ W1l,
                                              const float* __restrict__ b1l)
{
    int e = blockIdx.z;
    int cnt = g_cnt[e];
    int m0 = blockIdx.y * BM;
    if (m0 >= cnt) return;
    int off = g_off[e];
    const float* Bm = W1l + (size_t)e * H * FF;
    const float* bias = b1l + (size_t)e * FF;

    __shared__ float As[BK][BM];
    __shared__ float Bs[BK][BN];
    int tid = threadIdx.x;
    int trow = tid >> 4, tcol = tid & 15;
    int n0 = blockIdx.x * BN;

    int ar0 = tid >> 2, ar1 = ar0 + 64;
    int acv = (tid & 3) * 4;
    int s0 = m0 + ar0, s1 = m0 + ar1;
    const float* Arow0 = (s0 < cnt) ? g_H1 + (size_t)g_perm[off + s0] * H : nullptr;
    const float* Arow1 = (s1 < cnt) ? g_H1 + (size_t)g_perm[off + s1] * H : nullptr;
    int blr = tid >> 4, blc = (tid & 15) * 4;

    float acc[TM][TN] = {};
    for (int kt = 0; kt < H; kt += BK) {
        float4 a0 = make_float4(0.f, 0.f, 0.f, 0.f), a1 = a0;
        if (Arow0) a0 = *(const float4*)(Arow0 + kt + acv);
        if (Arow1) a1 = *(const float4*)(Arow1 + kt + acv);
        float4 b4 = *(const float4*)(Bm + (size_t)(kt + blr) * FF + n0 + blc);
        As[acv + 0][ar0] = a0.x; As[acv + 1][ar0] = a0.y; As[acv + 2][ar0] = a0.z; As[acv + 3][ar0] = a0.w;
        As[acv + 0][ar1] = a1.x; As[acv + 1][ar1] = a1.y; As[acv + 2][ar1] = a1.z; As[acv + 3][ar1] = a1.w;
        *(float4*)&Bs[blr][blc] = b4;
        __syncthreads();
        #pragma unroll
        for (int k = 0; k < BK; k++) {
            float a[TM], bb[TN];
            *(float4*)&a[0] = *(float4*)&As[k][trow * TM];
            *(float4*)&a[4] = *(float4*)&As[k][trow * TM + 4];
            *(float4*)&bb[0] = *(float4*)&Bs[k][tcol * TN];
            #pragma unroll
            for (int i = 0; i < TM; i++)
                #pragma unroll
                for (int j = 0; j < TN; j++)
                    acc[i][j] += a[i] * bb[j];
        }
        __syncthreads();
    }
    #pragma unroll
    for (int i = 0; i < TM; i++) {
        int gm = m0 + trow * TM + i;
        if (gm >= cnt) continue;
        size_t r = (size_t)(off + gm) * FF + n0 + tcol * TN;
        #pragma unroll
        for (int j = 0; j < TN; j++) {
            float v = acc[i][j] + bias[n0 + tcol * TN + j];
            g_mid[r + j] = 0.5f * v * (1.0f + erff(v * 0.70710678118654752f));
        }
    }
}

// ---------------------------------------------------------------- FFN GEMM2 (residual scatter)
__global__ __launch_bounds__(256) void k_ffn2(const float* __restrict__ W2l,
                                              const float* __restrict__ b2l,
                                              float* __restrict__ x)
{
    int e = blockIdx.z;
    int cnt = g_cnt[e];
    int m0 = blockIdx.y * BM;
    if (m0 >= cnt) return;
    int off = g_off[e];
    const float* Bm = W2l + (size_t)e * FF * H;
    const float* bias = b2l + (size_t)e * H;

    __shared__ float As[BK][BM];
    __shared__ float Bs[BK][BN];
    int tid = threadIdx.x;
    int trow = tid >> 4, tcol = tid & 15;
    int n0 = blockIdx.x * BN;

    int ar0 = tid >> 2, ar1 = ar0 + 64;
    int acv = (tid & 3) * 4;
    int s0 = m0 + ar0, s1 = m0 + ar1;
    const float* Arow0 = (s0 < cnt) ? g_mid + (size_t)(off + s0) * FF : nullptr;
    const float* Arow1 = (s1 < cnt) ? g_mid + (size_t)(off + s1) * FF : nullptr;
    int blr = tid >> 4, blc = (tid & 15) * 4;

    float acc[TM][TN] = {};
    for (int kt = 0; kt < FF; kt += BK) {
        float4 a0 = make_float4(0.f, 0.f, 0.f, 0.f), a1 = a0;
        if (Arow0) a0 = *(const float4*)(Arow0 + kt + acv);
        if (Arow1) a1 = *(const float4*)(Arow1 + kt + acv);
        float4 b4 = *(const float4*)(Bm + (size_t)(kt + blr) * H + n0 + blc);
        As[acv + 0][ar0] = a0.x; As[acv + 1][ar0] = a0.y; As[acv + 2][ar0] = a0.z; As[acv + 3][ar0] = a0.w;
        As[acv + 0][ar1] = a1.x; As[acv + 1][ar1] = a1.y; As[acv + 2][ar1] = a1.z; As[acv + 3][ar1] = a1.w;
        *(float4*)&Bs[blr][blc] = b4;
        __syncthreads();
        #pragma unroll
        for (int k = 0; k < BK; k++) {
            float a[TM], bb[TN];
            *(float4*)&a[0] = *(float4*)&As[k][trow * TM];
            *(float4*)&a[4] = *(float4*)&As[k][trow * TM + 4];
            *(float4*)&bb[0] = *(float4*)&Bs[k][tcol * TN];
            #pragma unroll
            for (int i = 0; i < TM; i++)
                #pragma unroll
                for (int j = 0; j < TN; j++)
                    acc[i][j] += a[i] * bb[j];
        }
        __syncthreads();
    }
    #pragma unroll
    for (int i = 0; i < TM; i++) {
        int gm = m0 + trow * TM + i;
        if (gm >= cnt) continue;
        int token = g_perm[off + gm];
        size_t r = (size_t)token * H + n0 + tcol * TN;
        #pragma unroll
        for (int j = 0; j < TN; j++)
            x[r + j] = x[r + j] + acc[i][j] + bias[n0 + tcol * TN + j];
    }
}

// ---------------------------------------------------------------- launch
extern "C" void kernel_launch(void* const* d_in, const int* in_sizes, int n_in,
                              void* d_out, int out_size) {
    (void)in_sizes; (void)n_in; (void)out_size;
    const float* x_in  = (const float*)d_in[0];
    // d_in[1] = note_pos: identity permutation / all-valid mask — unused.
    const int*   ntp   = (const int*)d_in[2];
    const float* Wq    = (const float*)d_in[3];
    const float* bq    = (const float*)d_in[4];
    const float* Wk    = (const float*)d_in[5];
    const float* bk    = (const float*)d_in[6];
    const float* Wv    = (const float*)d_in[7];
    const float* bv    = (const float*)d_in[8];
    const float* ln1w  = (const float*)d_in[9];
    const float* ln1b  = (const float*)d_in[10];
    const float* ln2w  = (const float*)d_in[11];
    const float* ln2b  = (const float*)d_in[12];
    const float* W1    = (const float*)d_in[13];
    const float* b1    = (const float*)d_in[14];
    const float* W2    = (const float*)d_in[15];
    const float* b2    = (const float*)d_in[16];
    float* x = (float*)d_out;

    cudaFuncSetAttribute(k_attn, cudaFuncAttributeMaxDynamicSharedMemorySize, ATTN_SMEM);

    k_add_pe<<<(T * H + 255) / 256, 256>>>(x_in, x);
    k_route<<<1, 256>>>(ntp);

    for (int l = 0; l < Lr; l++) {
        k_ln<<<T, 256>>>(x, ln1w + l * H, ln1b + l * H);
        k_qkv<<<dim3(H / BN, T / BM, 3), 256>>>(
            Wq + (size_t)l * H * H, Wk + (size_t)l * H * H, Wv + (size_t)l * H * H,
            bq + l * H, bk + l * H, bv + l * H);
        k_attn<<<dim3(Sq / 64, NH, Bz), 256, ATTN_SMEM>>>(x);
        k_ln<<<T, 256>>>(x, ln2w + l * H, ln2b + l * H);
        k_ffn1<<<dim3(FF / BN, T / BM, NE), 256>>>(
            W1 + (size_t)l * NE * H * FF, b1 + (size_t)l * NE * FF);
        k_ffn2<<<dim3(H / BN, T / BM, NE), 256>>>(
            W2 + (size_t)l * NE * FF * H, b2 + (size_t)l * NE * H, x);
    }
}

// round 2
// speedup vs baseline: 1.8796x; 1.8796x over previous
#include <cuda_runtime.h>
#include <math.h>
#include <stdint.h>

// Problem constants
constexpr int Bz = 8, Sq = 256, H = 768, Lr = 2, NE = 4, FF = 3072;
constexpr int NH = 12, HD = 64;
constexpr int T = Bz * Sq;          // 2048 tokens
constexpr float EPS = 1e-5f;

// Scratch (static device allocations — allowed)
__device__ float g_H1[T * H];
__device__ float g_Qb[T * H];
__device__ float g_Kb[T * H];
__device__ float g_Vb[T * H];
__device__ float g_mid[(size_t)T * FF];
__device__ int   g_perm[T];
__device__ int   g_rank[T];
__device__ int   g_cnt[NE];
__device__ int   g_off[NE];

// ---------------------------------------------------------------- PE add
__global__ void k_add_pe(const float* __restrict__ xin, float* __restrict__ x) {
    int idx = blockIdx.x * blockDim.x + threadIdx.x;
    if (idx >= T * H) return;
    int d = idx % H;
    int s = (idx / H) % Sq;
    int i2 = d & ~1;
    float div = expf(-(float)i2 * (9.210340371976184f / (float)H)); // ln(10000)/H
    float ang = (float)s * div;
    float pe = (d & 1) ? cosf(ang) : sinf(ang);
    x[idx] = xin[idx] + pe;
}

// ---------------------------------------------------------------- routing
__global__ void k_route(const int* __restrict__ ntp) {
    __shared__ int scnt[NE];
    __shared__ int soff[NE];
    int tid = threadIdx.x;
    if (tid < NE) scnt[tid] = 0;
    __syncthreads();
    for (int t = tid; t < T; t += blockDim.x) {
        int e = ntp[t];
        g_rank[t] = atomicAdd(&scnt[e], 1);
    }
    __syncthreads();
    if (tid == 0) {
        int a = 0;
        for (int e = 0; e < NE; e++) {
            soff[e] = a; g_off[e] = a; g_cnt[e] = scnt[e]; a += scnt[e];
        }
    }
    __syncthreads();
    for (int t = tid; t < T; t += blockDim.x) {
        int e = ntp[t];
        g_perm[soff[e] + g_rank[t]] = t;
    }
}

// ---------------------------------------------------------------- layernorm
__device__ __forceinline__ float block_sum_768(float v) {
    __shared__ float red[8];
    int tid = threadIdx.x;
    #pragma unroll
    for (int o = 16; o; o >>= 1) v += __shfl_xor_sync(0xffffffffu, v, o);
    if ((tid & 31) == 0) red[tid >> 5] = v;
    __syncthreads();
    float t = 0.f;
    if (tid < 32) {
        t = (tid < 8) ? red[tid] : 0.f;
        #pragma unroll
        for (int o = 4; o; o >>= 1) t += __shfl_xor_sync(0xffffffffu, t, o);
        if (tid == 0) red[0] = t;
    }
    __syncthreads();
    float r = red[0];
    __syncthreads();
    return r;
}

__global__ __launch_bounds__(256) void k_ln(const float* __restrict__ x,
                                            const float* __restrict__ w,
                                            const float* __restrict__ b) {
    int row = blockIdx.x;
    int tid = threadIdx.x;
    const float* xr = x + (size_t)row * H;
    float v0 = xr[tid], v1 = xr[tid + 256], v2 = xr[tid + 512];
    float mu = block_sum_768(v0 + v1 + v2) * (1.0f / H);
    float d0 = v0 - mu, d1 = v1 - mu, d2 = v2 - mu;
    float var = block_sum_768(d0 * d0 + d1 * d1 + d2 * d2) * (1.0f / H);
    float rstd = rsqrtf(var + EPS);
    float* orow = g_H1 + (size_t)row * H;
    orow[tid]       = d0 * rstd * w[tid]       + b[tid];
    orow[tid + 256] = d1 * rstd * w[tid + 256] + b[tid + 256];
    orow[tid + 512] = d2 * rstd * w[tid + 512] + b[tid + 512];
}

// ---------------------------------------------------------------- tf32 GEMM core
// Block tile 128x128, 4 warps (2x2), warp tile 64x64, mma.sync m16n8k8 tf32.
// smem: As[2][128][20] (row-major [m][k], pad 20), Bs[2][16][132] ([k][n], pad 132).

__device__ __forceinline__ uint32_t f2tf(float f) {
    uint32_t u;
    asm("cvt.rna.tf32.f32 %0, %1;" : "=r"(u) : "f"(f));
    return u;
}

__device__ __forceinline__ void mma_tf32(float (&c)[4], const uint32_t (&a)[4], const uint32_t (&b)[2]) {
    asm volatile(
        "mma.sync.aligned.m16n8k8.row.col.f32.tf32.tf32.f32 "
        "{%0,%1,%2,%3},{%4,%5,%6,%7},{%8,%9},{%0,%1,%2,%3};"
        : "+f"(c[0]), "+f"(c[1]), "+f"(c[2]), "+f"(c[3])
        : "r"(a[0]), "r"(a[1]), "r"(a[2]), "r"(a[3]), "r"(b[0]), "r"(b[1]));
}

__device__ __forceinline__ void cp16(void* s, const void* g, int pred) {
    uint32_t sa = (uint32_t)__cvta_generic_to_shared(s);
    asm volatile(
        "{\n\t.reg .pred p;\n\t"
        "setp.ne.b32 p, %2, 0;\n\t"
        ".reg .b32 sz;\n\t"
        "selp.b32 sz, 16, 0, p;\n\t"
        "cp.async.ca.shared.global [%0], [%1], 16, sz;\n\t}"
        :: "r"(sa), "l"(g), "r"(pred));
}

__device__ __forceinline__ void gemm_mainloop(
    const float* __restrict__ Arow,   // per-thread A row pointer (clamped to valid memory)
    int avalid,
    const float* __restrict__ Bg, int ldB, int Kdim, int n0,
    float (&c)[4][8][4],
    float (*As)[128][20], float (*Bs)[16][132])
{
    int tid = threadIdx.x;
    int lane = tid & 31, warp = tid >> 5;
    int grp = lane >> 2, qid = lane & 3;
    int wm = (warp & 1) * 64, wn = (warp >> 1) * 64;

    int bk_[4], bn_[4];
    #pragma unroll
    for (int p = 0; p < 4; p++) { int idx = tid + p * 128; bk_[p] = idx >> 5; bn_[p] = (idx & 31) * 4; }

    int ntile = Kdim / 16;

    // prologue: stage tile 0
    #pragma unroll
    for (int v = 0; v < 4; v++)
        cp16(&As[0][tid][v * 4], Arow + v * 4, avalid);
    #pragma unroll
    for (int p = 0; p < 4; p++)
        cp16(&Bs[0][bk_[p]][bn_[p]], Bg + (size_t)bk_[p] * ldB + n0 + bn_[p], 1);
    asm volatile("cp.async.commit_group;");

    for (int t = 0; t < ntile; t++) {
        int buf = t & 1;
        if (t + 1 < ntile) {
            int nbuf = buf ^ 1;
            int kt = (t + 1) * 16;
            #pragma unroll
            for (int v = 0; v < 4; v++)
                cp16(&As[nbuf][tid][v * 4], Arow + kt + v * 4, avalid);
            #pragma unroll
            for (int p = 0; p < 4; p++)
                cp16(&Bs[nbuf][bk_[p]][bn_[p]], Bg + (size_t)(kt + bk_[p]) * ldB + n0 + bn_[p], 1);
            asm volatile("cp.async.commit_group;");
            asm volatile("cp.async.wait_group 1;");
        } else {
            asm volatile("cp.async.wait_group 0;");
        }
        __syncthreads();

        #pragma unroll
        for (int k0 = 0; k0 < 16; k0 += 8) {
            uint32_t at[4][4];
            #pragma unroll
            for (int fm = 0; fm < 4; fm++) {
                int m = wm + fm * 16 + grp;
                at[fm][0] = f2tf(As[buf][m    ][k0 + qid]);
                at[fm][1] = f2tf(As[buf][m + 8][k0 + qid]);
                at[fm][2] = f2tf(As[buf][m    ][k0 + qid + 4]);
                at[fm][3] = f2tf(As[buf][m + 8][k0 + qid + 4]);
            }
            uint32_t bt[8][2];
            #pragma unroll
            for (int fn = 0; fn < 8; fn++) {
                int n = wn + fn * 8 + grp;
                bt[fn][0] = f2tf(Bs[buf][k0 + qid    ][n]);
                bt[fn][1] = f2tf(Bs[buf][k0 + qid + 4][n]);
            }
            #pragma unroll
            for (int fm = 0; fm < 4; fm++)
                #pragma unroll
                for (int fn = 0; fn < 8; fn++)
                    mma_tf32(c[fm][fn], at[fm], bt[fn]);
        }
        __syncthreads();
    }
}

// ---------------------------------------------------------------- QKV GEMM (TC)
__global__ __launch_bounds__(128) void k_qkv_tc(
    const float* __restrict__ Wq, const float* __restrict__ Wk, const float* __restrict__ Wv,
    const float* __restrict__ bq, const float* __restrict__ bk, const float* __restrict__ bv)
{
    __shared__ float As[2][128][20];
    __shared__ float Bs[2][16][132];
    const float* Bg; const float* bias; float* C;
    if (blockIdx.z == 0)      { Bg = Wq; bias = bq; C = g_Qb; }
    else if (blockIdx.z == 1) { Bg = Wk; bias = bk; C = g_Kb; }
    else                      { Bg = Wv; bias = bv; C = g_Vb; }
    int m0 = blockIdx.y * 128, n0 = blockIdx.x * 128;
    const float* Arow = g_H1 + (size_t)(m0 + threadIdx.x) * H;
    float c[4][8][4] = {};
    gemm_mainloop(Arow, 1, Bg, H, H, n0, c, As, Bs);

    int lane = threadIdx.x & 31, warp = threadIdx.x >> 5;
    int grp = lane >> 2, qid = lane & 3;
    int wm = (warp & 1) * 64, wn = (warp >> 1) * 64;
    #pragma unroll
    for (int fn = 0; fn < 8; fn++) {
        int col = n0 + wn + fn * 8 + qid * 2;
        float bx = bias[col], by = bias[col + 1];
        #pragma unroll
        for (int fm = 0; fm < 4; fm++) {
            int m = m0 + wm + fm * 16 + grp;
            float2 v0 = make_float2(c[fm][fn][0] + bx, c[fm][fn][1] + by);
            float2 v1 = make_float2(c[fm][fn][2] + bx, c[fm][fn][3] + by);
            *(float2*)&C[(size_t)m * H + col] = v0;
            *(float2*)&C[(size_t)(m + 8) * H + col] = v1;
        }
    }
}

// ---------------------------------------------------------------- FFN GEMM1 (TC, gather + gelu)
__device__ __forceinline__ float gelu_f(float v) {
    return 0.5f * v * (1.0f + erff(v * 0.70710678118654752f));
}

__global__ __launch_bounds__(128) void k_ffn1_tc(const float* __restrict__ W1l,
                                                 const float* __restrict__ b1l)
{
    __shared__ float As[2][128][20];
    __shared__ float Bs[2][16][132];
    int e = blockIdx.z;
    int cnt = g_cnt[e];
    int m0 = blockIdx.y * 128;
    if (m0 >= cnt) return;
    int off = g_off[e];
    int n0 = blockIdx.x * 128;
    const float* Bg = W1l + (size_t)e * H * FF;
    const float* bias = b1l + (size_t)e * FF;

    int s = m0 + threadIdx.x;
    int valid = (s < cnt);
    const float* Arow = g_H1 + (size_t)(valid ? g_perm[off + s] : 0) * H;
    float c[4][8][4] = {};
    gemm_mainloop(Arow, valid, Bg, FF, H, n0, c, As, Bs);

    int lane = threadIdx.x & 31, warp = threadIdx.x >> 5;
    int grp = lane >> 2, qid = lane & 3;
    int wm = (warp & 1) * 64, wn = (warp >> 1) * 64;
    #pragma unroll
    for (int fn = 0; fn < 8; fn++) {
        int col = n0 + wn + fn * 8 + qid * 2;
        float bx = bias[col], by = bias[col + 1];
        #pragma unroll
        for (int fm = 0; fm < 4; fm++) {
            int gm = m0 + wm + fm * 16 + grp;
            if (gm < cnt) {
                size_t r = (size_t)(off + gm) * FF + col;
                g_mid[r]     = gelu_f(c[fm][fn][0] + bx);
                g_mid[r + 1] = gelu_f(c[fm][fn][1] + by);
            }
            if (gm + 8 < cnt) {
                size_t r = (size_t)(off + gm + 8) * FF + col;
                g_mid[r]     = gelu_f(c[fm][fn][2] + bx);
                g_mid[r + 1] = gelu_f(c[fm][fn][3] + by);
            }
        }
    }
}

// ---------------------------------------------------------------- FFN GEMM2 (TC, residual scatter)
__global__ __launch_bounds__(128) void k_ffn2_tc(const float* __restrict__ W2l,
                                                 const float* __restrict__ b2l,
                                                 float* __restrict__ x)
{
    __shared__ float As[2][128][20];
    __shared__ float Bs[2][16][132];
    int e = blockIdx.z;
    int cnt = g_cnt[e];
    int m0 = blockIdx.y * 128;
    if (m0 >= cnt) return;
    int off = g_off[e];
    int n0 = blockIdx.x * 128;
    const float* Bg = W2l + (size_t)e * FF * H;
    const float* bias = b2l + (size_t)e * H;

    int s = m0 + threadIdx.x;
    int valid = (s < cnt);
    const float* Arow = g_mid + (size_t)(off + (valid ? s : m0)) * FF;
    float c[4][8][4] = {};
    gemm_mainloop(Arow, valid, Bg, H, FF, n0, c, As, Bs);

    int lane = threadIdx.x & 31, warp = threadIdx.x >> 5;
    int grp = lane >> 2, qid = lane & 3;
    int wm = (warp & 1) * 64, wn = (warp >> 1) * 64;

    int tok0[4], tok1[4];
    #pragma unroll
    for (int fm = 0; fm < 4; fm++) {
        int gm = m0 + wm + fm * 16 + grp;
        tok0[fm] = (gm < cnt)     ? g_perm[off + gm]     : -1;
        tok1[fm] = (gm + 8 < cnt) ? g_perm[off + gm + 8] : -1;
    }
    #pragma unroll
    for (int fn = 0; fn < 8; fn++) {
        int col = n0 + wn + fn * 8 + qid * 2;
        float bx = bias[col], by = bias[col + 1];
        #pragma unroll
        for (int fm = 0; fm < 4; fm++) {
            if (tok0[fm] >= 0) {
                float* p = &x[(size_t)tok0[fm] * H + col];
                p[0] += c[fm][fn][0] + bx;
                p[1] += c[fm][fn][1] + by;
            }
            if (tok1[fm] >= 0) {
                float* p = &x[(size_t)tok1[fm] * H + col];
                p[0] += c[fm][fn][2] + bx;
                p[1] += c[fm][fn][3] + by;
            }
        }
    }
}

// ---------------------------------------------------------------- attention (fp32, unchanged)
constexpr int ATTN_SMEM = (64 * 65 + 256 * 65 + 256 * 65) * 4;

__global__ __launch_bounds__(256) void k_attn(float* __restrict__ x) {
    extern __shared__ float sm[];
    float* Qs = sm;
    float* Ks = sm + 64 * 65;
    float* Vs = sm + 64 * 65 + 256 * 65;
    int qt = blockIdx.x, hd = blockIdx.y, b = blockIdx.z;
    int tid = threadIdx.x;
    int hoff = hd * HD;

    for (int v = tid; v < 64 * 16; v += 256) {
        int r = v >> 4, cv = (v & 15) * 4;
        float4 t4 = *(const float4*)(g_Qb + (size_t)(b * Sq + qt * 64 + r) * H + hoff + cv);
        Qs[r * 65 + cv + 0] = t4.x; Qs[r * 65 + cv + 1] = t4.y;
        Qs[r * 65 + cv + 2] = t4.z; Qs[r * 65 + cv + 3] = t4.w;
    }
    for (int v = tid; v < 256 * 16; v += 256) {
        int r = v >> 4, cv = (v & 15) * 4;
        float4 k4 = *(const float4*)(g_Kb + (size_t)(b * Sq + r) * H + hoff + cv);
        Ks[r * 65 + cv + 0] = k4.x; Ks[r * 65 + cv + 1] = k4.y;
        Ks[r * 65 + cv + 2] = k4.z; Ks[r * 65 + cv + 3] = k4.w;
        float4 v4 = *(const float4*)(g_Vb + (size_t)(b * Sq + r) * H + hoff + cv);
        Vs[r * 65 + cv + 0] = v4.x; Vs[r * 65 + cv + 1] = v4.y;
        Vs[r * 65 + cv + 2] = v4.z; Vs[r * 65 + cv + 3] = v4.w;
    }
    __syncthreads();

    int w = tid >> 5, tc = tid & 31;
    float sc[8][8];
    #pragma unroll
    for (int i = 0; i < 8; i++)
        #pragma unroll
        for (int j = 0; j < 8; j++) sc[i][j] = 0.f;

    #pragma unroll 4
    for (int d = 0; d < HD; d++) {
        float a[8], bb[8];
        #pragma unroll
        for (int i = 0; i < 8; i++) a[i] = Qs[(w * 8 + i) * 65 + d];
        #pragma unroll
        for (int j = 0; j < 8; j++) bb[j] = Ks[(tc + 32 * j) * 65 + d];
        #pragma unroll
        for (int i = 0; i < 8; i++)
            #pragma unroll
            for (int j = 0; j < 8; j++) sc[i][j] += a[i] * bb[j];
    }
    __syncthreads();   // everyone done reading Ks before we overwrite as P

    float* Ps = Ks;    // 64 x 256
    #pragma unroll
    for (int i = 0; i < 8; i++) {
        float m = -1e30f;
        #pragma unroll
        for (int j = 0; j < 8; j++) m = fmaxf(m, sc[i][j]);
        #pragma unroll
        for (int o = 16; o; o >>= 1) m = fmaxf(m, __shfl_xor_sync(0xffffffffu, m, o));
        float s = 0.f;
        #pragma unroll
        for (int j = 0; j < 8; j++) { sc[i][j] = expf(sc[i][j] - m); s += sc[i][j]; }
        #pragma unroll
        for (int o = 16; o; o >>= 1) s += __shfl_xor_sync(0xffffffffu, s, o);
        float inv = 1.f / s;
        #pragma unroll
        for (int j = 0; j < 8; j++)
            Ps[(w * 8 + i) * 256 + tc + 32 * j] = sc[i][j] * inv;
    }
    __syncthreads();

    int tr2 = tid >> 4, tc2 = tid & 15;
    float o[4][4] = {};
    #pragma unroll 4
    for (int kk = 0; kk < Sq; kk++) {
        float a[4], bb[4];
        #pragma unroll
        for (int i = 0; i < 4; i++) a[i] = Ps[(tr2 * 4 + i) * 256 + kk];
        #pragma unroll
        for (int j = 0; j < 4; j++) bb[j] = Vs[kk * 65 + tc2 * 4 + j];
        #pragma unroll
        for (int i = 0; i < 4; i++)
            #pragma unroll
            for (int j = 0; j < 4; j++) o[i][j] += a[i] * bb[j];
    }
    #pragma unroll
    for (int i = 0; i < 4; i++) {
        size_t r = (size_t)(b * Sq + qt * 64 + tr2 * 4 + i) * H + hoff + tc2 * 4;
        #pragma unroll
        for (int j = 0; j < 4; j++) x[r + j] += o[i][j];
    }
}

// ---------------------------------------------------------------- launch
extern "C" void kernel_launch(void* const* d_in, const int* in_sizes, int n_in,
                              void* d_out, int out_size) {
    (void)in_sizes; (void)n_in; (void)out_size;
    const float* x_in  = (const float*)d_in[0];
    // d_in[1] = note_pos: identity permutation / all-valid mask — unused.
    const int*   ntp   = (const int*)d_in[2];
    const float* Wq    = (const float*)d_in[3];
    const float* bq    = (const float*)d_in[4];
    const float* Wk    = (const float*)d_in[5];
    const float* bk    = (const float*)d_in[6];
    const float* Wv    = (const float*)d_in[7];
    const float* bv    = (const float*)d_in[8];
    const float* ln1w  = (const float*)d_in[9];
    const float* ln1b  = (const float*)d_in[10];
    const float* ln2w  = (const float*)d_in[11];
    const float* ln2b  = (const float*)d_in[12];
    const float* W1    = (const float*)d_in[13];
    const float* b1    = (const float*)d_in[14];
    const float* W2    = (const float*)d_in[15];
    const float* b2    = (const float*)d_in[16];
    float* x = (float*)d_out;

    cudaFuncSetAttribute(k_attn, cudaFuncAttributeMaxDynamicSharedMemorySize, ATTN_SMEM);

    k_add_pe<<<(T * H + 255) / 256, 256>>>(x_in, x);
    k_route<<<1, 256>>>(ntp);

    for (int l = 0; l < Lr; l++) {
        k_ln<<<T, 256>>>(x, ln1w + l * H, ln1b + l * H);
        k_qkv_tc<<<dim3(H / 128, T / 128, 3), 128>>>(
            Wq + (size_t)l * H * H, Wk + (size_t)l * H * H, Wv + (size_t)l * H * H,
            bq + l * H, bk + l * H, bv + l * H);
        k_attn<<<dim3(Sq / 64, NH, Bz), 256, ATTN_SMEM>>>(x);
        k_ln<<<T, 256>>>(x, ln2w + l * H, ln2b + l * H);
        k_ffn1_tc<<<dim3(FF / 128, T / 128, NE), 128>>>(
            W1 + (size_t)l * NE * H * FF, b1 + (size_t)l * NE * FF);
        k_ffn2_tc<<<dim3(H / 128, T / 128, NE), 128>>>(
            W2 + (size_t)l * NE * FF * H, b2 + (size_t)l * NE * H, x);
    }
}

// round 3
// speedup vs baseline: 2.2724x; 1.2090x over previous
#include <cuda_runtime.h>
#include <math.h>
#include <stdint.h>

// Problem constants
constexpr int Bz = 8, Sq = 256, H = 768, Lr = 2, NE = 4, FF = 3072;
constexpr int NH = 12, HD = 64;
constexpr int T = Bz * Sq;          // 2048 tokens
constexpr float EPS = 1e-5f;

// Scratch
__device__ float g_H1[T * H];
__device__ float g_Qb[T * H];
__device__ float g_Kb[T * H];
__device__ float g_Vb[T * H];
__device__ float g_mid[(size_t)T * FF];
__device__ int   g_perm[T];
__device__ int   g_rank[T];
__device__ int   g_cnt[NE];
__device__ int   g_off[NE];

// ---------------------------------------------------------------- PE add
__global__ void k_add_pe(const float* __restrict__ xin, float* __restrict__ x) {
    int idx = blockIdx.x * blockDim.x + threadIdx.x;
    if (idx >= T * H) return;
    int d = idx % H;
    int s = (idx / H) % Sq;
    int i2 = d & ~1;
    float div = expf(-(float)i2 * (9.210340371976184f / (float)H));
    float ang = (float)s * div;
    float pe = (d & 1) ? cosf(ang) : sinf(ang);
    x[idx] = xin[idx] + pe;
}

// ---------------------------------------------------------------- routing
__global__ void k_route(const int* __restrict__ ntp) {
    __shared__ int scnt[NE];
    __shared__ int soff[NE];
    int tid = threadIdx.x;
    if (tid < NE) scnt[tid] = 0;
    __syncthreads();
    for (int t = tid; t < T; t += blockDim.x) {
        int e = ntp[t];
        g_rank[t] = atomicAdd(&scnt[e], 1);
    }
    __syncthreads();
    if (tid == 0) {
        int a = 0;
        for (int e = 0; e < NE; e++) {
            soff[e] = a; g_off[e] = a; g_cnt[e] = scnt[e]; a += scnt[e];
        }
    }
    __syncthreads();
    for (int t = tid; t < T; t += blockDim.x) {
        int e = ntp[t];
        g_perm[soff[e] + g_rank[t]] = t;
    }
}

// ---------------------------------------------------------------- layernorm
__device__ __forceinline__ float block_sum_768(float v) {
    __shared__ float red[8];
    int tid = threadIdx.x;
    #pragma unroll
    for (int o = 16; o; o >>= 1) v += __shfl_xor_sync(0xffffffffu, v, o);
    if ((tid & 31) == 0) red[tid >> 5] = v;
    __syncthreads();
    float t = 0.f;
    if (tid < 32) {
        t = (tid < 8) ? red[tid] : 0.f;
        #pragma unroll
        for (int o = 4; o; o >>= 1) t += __shfl_xor_sync(0xffffffffu, t, o);
        if (tid == 0) red[0] = t;
    }
    __syncthreads();
    float r = red[0];
    __syncthreads();
    return r;
}

__global__ __launch_bounds__(256) void k_ln(const float* __restrict__ x,
                                            const float* __restrict__ w,
                                            const float* __restrict__ b) {
    int row = blockIdx.x;
    int tid = threadIdx.x;
    const float* xr = x + (size_t)row * H;
    float v0 = xr[tid], v1 = xr[tid + 256], v2 = xr[tid + 512];
    float mu = block_sum_768(v0 + v1 + v2) * (1.0f / H);
    float d0 = v0 - mu, d1 = v1 - mu, d2 = v2 - mu;
    float var = block_sum_768(d0 * d0 + d1 * d1 + d2 * d2) * (1.0f / H);
    float rstd = rsqrtf(var + EPS);
    float* orow = g_H1 + (size_t)row * H;
    orow[tid]       = d0 * rstd * w[tid]       + b[tid];
    orow[tid + 256] = d1 * rstd * w[tid + 256] + b[tid + 256];
    orow[tid + 512] = d2 * rstd * w[tid + 512] + b[tid + 512];
}

// ---------------------------------------------------------------- mma helpers
__device__ __forceinline__ uint32_t f2tf(float f) {
    uint32_t u;
    asm("cvt.rna.tf32.f32 %0, %1;" : "=r"(u) : "f"(f));
    return u;
}

__device__ __forceinline__ void mma_tf32(float (&c)[4], const uint32_t (&a)[4], const uint32_t (&b)[2]) {
    asm volatile(
        "mma.sync.aligned.m16n8k8.row.col.f32.tf32.tf32.f32 "
        "{%0,%1,%2,%3},{%4,%5,%6,%7},{%8,%9},{%0,%1,%2,%3};"
        : "+f"(c[0]), "+f"(c[1]), "+f"(c[2]), "+f"(c[3])
        : "r"(a[0]), "r"(a[1]), "r"(a[2]), "r"(a[3]), "r"(b[0]), "r"(b[1]));
}

__device__ __forceinline__ void cp16(void* s, const void* g, int pred) {
    uint32_t sa = (uint32_t)__cvta_generic_to_shared(s);
    asm volatile(
        "{\n\t.reg .pred p;\n\t"
        "setp.ne.b32 p, %2, 0;\n\t"
        ".reg .b32 sz;\n\t"
        "selp.b32 sz, 16, 0, p;\n\t"
        "cp.async.ca.shared.global [%0], [%1], 16, sz;\n\t}"
        :: "r"(sa), "l"(g), "r"(pred));
}

// ---------------------------------------------------------------- tf32 GEMM core (256 thr)
// Block tile 128x128, 8 warps 2x4, warp tile 64x32, mma m16n8k8, BK=16, 2-stage cp.async.
__device__ __forceinline__ void gemm_mainloop256(
    const float* __restrict__ Arow,   // base pointer of this thread's A row (valid memory)
    int avalid,
    const float* __restrict__ Bg, int ldB, int Kdim, int n0,
    float (&c)[4][4][4],
    float (*As)[128][20], float (*Bs)[16][132])
{
    int tid = threadIdx.x;
    int lane = tid & 31, warp = tid >> 5;
    int grp = lane >> 2, qid = lane & 3;
    int wm = (warp & 1) * 64, wn = (warp >> 1) * 32;
    int arow = tid >> 1, acv = (tid & 1) * 8;
    int bk = tid >> 4, bn = (tid & 15) * 8;
    int ntile = Kdim / 16;

    cp16(&As[0][arow][acv],     Arow + acv,     avalid);
    cp16(&As[0][arow][acv + 4], Arow + acv + 4, avalid);
    cp16(&Bs[0][bk][bn],     Bg + (size_t)bk * ldB + n0 + bn,     1);
    cp16(&Bs[0][bk][bn + 4], Bg + (size_t)bk * ldB + n0 + bn + 4, 1);
    asm volatile("cp.async.commit_group;");

    for (int t = 0; t < ntile; t++) {
        int buf = t & 1;
        if (t + 1 < ntile) {
            int nbuf = buf ^ 1;
            int kt = (t + 1) * 16;
            cp16(&As[nbuf][arow][acv],     Arow + kt + acv,     avalid);
            cp16(&As[nbuf][arow][acv + 4], Arow + kt + acv + 4, avalid);
            cp16(&Bs[nbuf][bk][bn],     Bg + (size_t)(kt + bk) * ldB + n0 + bn,     1);
            cp16(&Bs[nbuf][bk][bn + 4], Bg + (size_t)(kt + bk) * ldB + n0 + bn + 4, 1);
            asm volatile("cp.async.commit_group;");
            asm volatile("cp.async.wait_group 1;");
        } else {
            asm volatile("cp.async.wait_group 0;");
        }
        __syncthreads();

        #pragma unroll
        for (int k0 = 0; k0 < 16; k0 += 8) {
            uint32_t at[4][4];
            #pragma unroll
            for (int fm = 0; fm < 4; fm++) {
                int mm = wm + fm * 16 + grp;
                at[fm][0] = f2tf(As[buf][mm    ][k0 + qid]);
                at[fm][1] = f2tf(As[buf][mm + 8][k0 + qid]);
                at[fm][2] = f2tf(As[buf][mm    ][k0 + qid + 4]);
                at[fm][3] = f2tf(As[buf][mm + 8][k0 + qid + 4]);
            }
            uint32_t bt[4][2];
            #pragma unroll
            for (int fn = 0; fn < 4; fn++) {
                int nn = wn + fn * 8 + grp;
                bt[fn][0] = f2tf(Bs[buf][k0 + qid    ][nn]);
                bt[fn][1] = f2tf(Bs[buf][k0 + qid + 4][nn]);
            }
            #pragma unroll
            for (int fm = 0; fm < 4; fm++)
                #pragma unroll
                for (int fn = 0; fn < 4; fn++)
                    mma_tf32(c[fm][fn], at[fm], bt[fn]);
        }
        __syncthreads();
    }
}

// ---------------------------------------------------------------- QKV GEMM (TC)
__global__ __launch_bounds__(256, 2) void k_qkv_tc(
    const float* __restrict__ Wq, const float* __restrict__ Wk, const float* __restrict__ Wv,
    const float* __restrict__ bq, const float* __restrict__ bk, const float* __restrict__ bv)
{
    __shared__ float As[2][128][20];
    __shared__ float Bs[2][16][132];
    const float* Bg; const float* bias; float* C;
    if (blockIdx.z == 0)      { Bg = Wq; bias = bq; C = g_Qb; }
    else if (blockIdx.z == 1) { Bg = Wk; bias = bk; C = g_Kb; }
    else                      { Bg = Wv; bias = bv; C = g_Vb; }
    int m0 = blockIdx.y * 128, n0 = blockIdx.x * 128;
    const float* Arow = g_H1 + (size_t)(m0 + (threadIdx.x >> 1)) * H;
    float c[4][4][4] = {};
    gemm_mainloop256(Arow, 1, Bg, H, H, n0, c, As, Bs);

    int lane = threadIdx.x & 31, warp = threadIdx.x >> 5;
    int grp = lane >> 2, qid = lane & 3;
    int wm = (warp & 1) * 64, wn = (warp >> 1) * 32;
    #pragma unroll
    for (int fn = 0; fn < 4; fn++) {
        int col = n0 + wn + fn * 8 + qid * 2;
        float bx = bias[col], by = bias[col + 1];
        #pragma unroll
        for (int fm = 0; fm < 4; fm++) {
            int m = m0 + wm + fm * 16 + grp;
            *(float2*)&C[(size_t)m * H + col]       = make_float2(c[fm][fn][0] + bx, c[fm][fn][1] + by);
            *(float2*)&C[(size_t)(m + 8) * H + col] = make_float2(c[fm][fn][2] + bx, c[fm][fn][3] + by);
        }
    }
}

// ---------------------------------------------------------------- FFN GEMM1 (gather + gelu)
__device__ __forceinline__ float gelu_f(float v) {
    return 0.5f * v * (1.0f + erff(v * 0.70710678118654752f));
}

__global__ __launch_bounds__(256, 2) void k_ffn1_tc(const float* __restrict__ W1l,
                                                    const float* __restrict__ b1l)
{
    __shared__ float As[2][128][20];
    __shared__ float Bs[2][16][132];
    int e = blockIdx.z;
    int cnt = g_cnt[e];
    int m0 = blockIdx.y * 128;
    if (m0 >= cnt) return;
    int off = g_off[e];
    int n0 = blockIdx.x * 128;
    const float* Bg = W1l + (size_t)e * H * FF;
    const float* bias = b1l + (size_t)e * FF;

    int s = m0 + (threadIdx.x >> 1);
    int valid = (s < cnt);
    const float* Arow = g_H1 + (size_t)(valid ? g_perm[off + s] : 0) * H;
    float c[4][4][4] = {};
    gemm_mainloop256(Arow, valid, Bg, FF, H, n0, c, As, Bs);

    int lane = threadIdx.x & 31, warp = threadIdx.x >> 5;
    int grp = lane >> 2, qid = lane & 3;
    int wm = (warp & 1) * 64, wn = (warp >> 1) * 32;
    #pragma unroll
    for (int fn = 0; fn < 4; fn++) {
        int col = n0 + wn + fn * 8 + qid * 2;
        float bx = bias[col], by = bias[col + 1];
        #pragma unroll
        for (int fm = 0; fm < 4; fm++) {
            int gm = m0 + wm + fm * 16 + grp;
            if (gm < cnt) {
                size_t r = (size_t)(off + gm) * FF + col;
                g_mid[r]     = gelu_f(c[fm][fn][0] + bx);
                g_mid[r + 1] = gelu_f(c[fm][fn][1] + by);
            }
            if (gm + 8 < cnt) {
                size_t r = (size_t)(off + gm + 8) * FF + col;
                g_mid[r]     = gelu_f(c[fm][fn][2] + bx);
                g_mid[r + 1] = gelu_f(c[fm][fn][3] + by);
            }
        }
    }
}

// ---------------------------------------------------------------- FFN GEMM2 (residual scatter)
__global__ __launch_bounds__(256, 2) void k_ffn2_tc(const float* __restrict__ W2l,
                                                    const float* __restrict__ b2l,
                                                    float* __restrict__ x)
{
    __shared__ float As[2][128][20];
    __shared__ float Bs[2][16][132];
    int e = blockIdx.z;
    int cnt = g_cnt[e];
    int m0 = blockIdx.y * 128;
    if (m0 >= cnt) return;
    int off = g_off[e];
    int n0 = blockIdx.x * 128;
    const float* Bg = W2l + (size_t)e * FF * H;
    const float* bias = b2l + (size_t)e * H;

    int s = m0 + (threadIdx.x >> 1);
    int valid = (s < cnt);
    const float* Arow = g_mid + (size_t)(off + (valid ? s : m0)) * FF;
    float c[4][4][4] = {};
    gemm_mainloop256(Arow, valid, Bg, H, FF, n0, c, As, Bs);

    int lane = threadIdx.x & 31, warp = threadIdx.x >> 5;
    int grp = lane >> 2, qid = lane & 3;
    int wm = (warp & 1) * 64, wn = (warp >> 1) * 32;

    int tok0[4], tok1[4];
    #pragma unroll
    for (int fm = 0; fm < 4; fm++) {
        int gm = m0 + wm + fm * 16 + grp;
        tok0[fm] = (gm < cnt)     ? g_perm[off + gm]     : -1;
        tok1[fm] = (gm + 8 < cnt) ? g_perm[off + gm + 8] : -1;
    }
    #pragma unroll
    for (int fn = 0; fn < 4; fn++) {
        int col = n0 + wn + fn * 8 + qid * 2;
        float bx = bias[col], by = bias[col + 1];
        #pragma unroll
        for (int fm = 0; fm < 4; fm++) {
            if (tok0[fm] >= 0) {
                float* p = &x[(size_t)tok0[fm] * H + col];
                p[0] += c[fm][fn][0] + bx;
                p[1] += c[fm][fn][1] + by;
            }
            if (tok1[fm] >= 0) {
                float* p = &x[(size_t)tok1[fm] * H + col];
                p[0] += c[fm][fn][2] + bx;
                p[1] += c[fm][fn][3] + by;
            }
        }
    }
}

// ---------------------------------------------------------------- attention (tensor cores)
// block = (64-row q-tile, head, batch), 128 threads / 4 warps. Warp w owns rows [w*16, w*16+16).
// smem: Qs[64][68], Ks[256][68] (reused as Ps[64][260]), Vs[256][72]. All fragment LDS conflict-free.
constexpr int QPAD = 68, KPAD = 68, VPAD = 72, PPAD = 260;
constexpr int ATTN_SMEM = (64 * QPAD + 256 * KPAD + 256 * VPAD) * 4;

__global__ __launch_bounds__(128) void k_attn_tc(float* __restrict__ x) {
    extern __shared__ float sm[];
    float* Qs = sm;
    float* Ks = sm + 64 * QPAD;
    float* Vs = sm + 64 * QPAD + 256 * KPAD;
    float* Ps = Ks;  // 64 x 260 overlays Ks (16640 <= 17408 floats)
    int qt = blockIdx.x, hd = blockIdx.y, b = blockIdx.z;
    int tid = threadIdx.x;
    int lane = tid & 31, warp = tid >> 5;
    int grp = lane >> 2, qid = lane & 3;
    int hoff = hd * HD;
    int m = warp * 16;

    for (int v = tid; v < 64 * 16; v += 128) {
        int r = v >> 4, cv = (v & 15) * 4;
        float4 q4 = *(const float4*)(g_Qb + (size_t)(b * Sq + qt * 64 + r) * H + hoff + cv);
        Qs[r * QPAD + cv + 0] = q4.x; Qs[r * QPAD + cv + 1] = q4.y;
        Qs[r * QPAD + cv + 2] = q4.z; Qs[r * QPAD + cv + 3] = q4.w;
    }
    for (int v = tid; v < 256 * 16; v += 128) {
        int r = v >> 4, cv = (v & 15) * 4;
        float4 k4 = *(const float4*)(g_Kb + (size_t)(b * Sq + r) * H + hoff + cv);
        Ks[r * KPAD + cv + 0] = k4.x; Ks[r * KPAD + cv + 1] = k4.y;
        Ks[r * KPAD + cv + 2] = k4.z; Ks[r * KPAD + cv + 3] = k4.w;
        float4 v4 = *(const float4*)(g_Vb + (size_t)(b * Sq + r) * H + hoff + cv);
        Vs[r * VPAD + cv + 0] = v4.x; Vs[r * VPAD + cv + 1] = v4.y;
        Vs[r * VPAD + cv + 2] = v4.z; Vs[r * VPAD + cv + 3] = v4.w;
    }
    __syncthreads();

    // ---- scores: warp tile 16x256, K=64.  B = K^T so b-frag = Ks[n][k].
    float c[32][4];
    #pragma unroll
    for (int fn = 0; fn < 32; fn++)
        #pragma unroll
        for (int j = 0; j < 4; j++) c[fn][j] = 0.f;

    #pragma unroll
    for (int k0 = 0; k0 < 64; k0 += 8) {
        uint32_t at[4];
        at[0] = f2tf(Qs[(m + grp    ) * QPAD + k0 + qid]);
        at[1] = f2tf(Qs[(m + grp + 8) * QPAD + k0 + qid]);
        at[2] = f2tf(Qs[(m + grp    ) * QPAD + k0 + qid + 4]);
        at[3] = f2tf(Qs[(m + grp + 8) * QPAD + k0 + qid + 4]);
        #pragma unroll
        for (int fn = 0; fn < 32; fn++) {
            uint32_t bt[2];
            bt[0] = f2tf(Ks[(fn * 8 + grp) * KPAD + k0 + qid]);
            bt[1] = f2tf(Ks[(fn * 8 + grp) * KPAD + k0 + qid + 4]);
            mma_tf32(c[fn], at, bt);
        }
    }
    __syncthreads();  // done reading Ks before overwrite as Ps

    // ---- softmax over rows r0 = m+grp (c[..][0,1]) and r1 = r0+8 (c[..][2,3]); quad holds full row
    float mx0 = -1e30f, mx1 = -1e30f;
    #pragma unroll
    for (int fn = 0; fn < 32; fn++) {
        mx0 = fmaxf(mx0, fmaxf(c[fn][0], c[fn][1]));
        mx1 = fmaxf(mx1, fmaxf(c[fn][2], c[fn][3]));
    }
    #pragma unroll
    for (int o = 1; o <= 2; o <<= 1) {
        mx0 = fmaxf(mx0, __shfl_xor_sync(0xffffffffu, mx0, o));
        mx1 = fmaxf(mx1, __shfl_xor_sync(0xffffffffu, mx1, o));
    }
    float s0 = 0.f, s1 = 0.f;
    #pragma unroll
    for (int fn = 0; fn < 32; fn++) {
        c[fn][0] = __expf(c[fn][0] - mx0); s0 += c[fn][0];
        c[fn][1] = __expf(c[fn][1] - mx0); s0 += c[fn][1];
        c[fn][2] = __expf(c[fn][2] - mx1); s1 += c[fn][2];
        c[fn][3] = __expf(c[fn][3] - mx1); s1 += c[fn][3];
    }
    #pragma unroll
    for (int o = 1; o <= 2; o <<= 1) {
        s0 += __shfl_xor_sync(0xffffffffu, s0, o);
        s1 += __shfl_xor_sync(0xffffffffu, s1, o);
    }
    float inv0 = 1.f / s0, inv1 = 1.f / s1;
    #pragma unroll
    for (int fn = 0; fn < 32; fn++) {
        int col = fn * 8 + qid * 2;
        *(float2*)&Ps[(m + grp    ) * PPAD + col] = make_float2(c[fn][0] * inv0, c[fn][1] * inv0);
        *(float2*)&Ps[(m + grp + 8) * PPAD + col] = make_float2(c[fn][2] * inv1, c[fn][3] * inv1);
    }
    __syncthreads();

    // ---- PV: warp tile 16x64, K=256
    float c2[8][4];
    #pragma unroll
    for (int fn = 0; fn < 8; fn++)
        #pragma unroll
        for (int j = 0; j < 4; j++) c2[fn][j] = 0.f;

    #pragma unroll 4
    for (int k0 = 0; k0 < 256; k0 += 8) {
        uint32_t at[4];
        at[0] = f2tf(Ps[(m + grp    ) * PPAD + k0 + qid]);
        at[1] = f2tf(Ps[(m + grp + 8) * PPAD + k0 + qid]);
        at[2] = f2tf(Ps[(m + grp    ) * PPAD + k0 + qid + 4]);
        at[3] = f2tf(Ps[(m + grp + 8) * PPAD + k0 + qid + 4]);
        #pragma unroll
        for (int fn = 0; fn < 8; fn++) {
            uint32_t bt[2];
            bt[0] = f2tf(Vs[(k0 + qid    ) * VPAD + fn * 8 + grp]);
            bt[1] = f2tf(Vs[(k0 + qid + 4) * VPAD + fn * 8 + grp]);
            mma_tf32(c2[fn], at, bt);
        }
    }

    // ---- epilogue: x += ctx
    #pragma unroll
    for (int fn = 0; fn < 8; fn++) {
        int col = hoff + fn * 8 + qid * 2;
        size_t r0 = (size_t)(b * Sq + qt * 64 + m + grp) * H + col;
        size_t r1 = r0 + (size_t)8 * H;
        float2 v0 = *(float2*)&x[r0];
        v0.x += c2[fn][0]; v0.y += c2[fn][1];
        *(float2*)&x[r0] = v0;
        float2 v1 = *(float2*)&x[r1];
        v1.x += c2[fn][2]; v1.y += c2[fn][3];
        *(float2*)&x[r1] = v1;
    }
}

// ---------------------------------------------------------------- launch
extern "C" void kernel_launch(void* const* d_in, const int* in_sizes, int n_in,
                              void* d_out, int out_size) {
    (void)in_sizes; (void)n_in; (void)out_size;
    const float* x_in  = (const float*)d_in[0];
    const int*   ntp   = (const int*)d_in[2];
    const float* Wq    = (const float*)d_in[3];
    const float* bq    = (const float*)d_in[4];
    const float* Wk    = (const float*)d_in[5];
    const float* bk    = (const float*)d_in[6];
    const float* Wv    = (const float*)d_in[7];
    const float* bv    = (const float*)d_in[8];
    const float* ln1w  = (const float*)d_in[9];
    const float* ln1b  = (const float*)d_in[10];
    const float* ln2w  = (const float*)d_in[11];
    const float* ln2b  = (const float*)d_in[12];
    const float* W1    = (const float*)d_in[13];
    const float* b1    = (const float*)d_in[14];
    const float* W2    = (const float*)d_in[15];
    const float* b2    = (const float*)d_in[16];
    float* x = (float*)d_out;

    cudaFuncSetAttribute(k_attn_tc, cudaFuncAttributeMaxDynamicSharedMemorySize, ATTN_SMEM);

    k_add_pe<<<(T * H + 255) / 256, 256>>>(x_in, x);
    k_route<<<1, 256>>>(ntp);

    for (int l = 0; l < Lr; l++) {
        k_ln<<<T, 256>>>(x, ln1w + l * H, ln1b + l * H);
        k_qkv_tc<<<dim3(H / 128, T / 128, 3), 256>>>(
            Wq + (size_t)l * H * H, Wk + (size_t)l * H * H, Wv + (size_t)l * H * H,
            bq + l * H, bk + l * H, bv + l * H);
        k_attn_tc<<<dim3(Sq / 64, NH, Bz), 128, ATTN_SMEM>>>(x);
        k_ln<<<T, 256>>>(x, ln2w + l * H, ln2b + l * H);
        k_ffn1_tc<<<dim3(FF / 128, T / 128, NE), 256>>>(
            W1 + (size_t)l * NE * H * FF, b1 + (size_t)l * NE * FF);
        k_ffn2_tc<<<dim3(H / 128, T / 128, NE), 256>>>(
            W2 + (size_t)l * NE * FF * H, b2 + (size_t)l * NE * H, x);
    }
}

// round 4
// speedup vs baseline: 2.7022x; 1.1891x over previous
#include <cuda_runtime.h>
#include <math.h>
#include <stdint.h>

// Problem constants
constexpr int Bz = 8, Sq = 256, H = 768, Lr = 2, NE = 4, FF = 3072;
constexpr int NH = 12, HD = 64;
constexpr int T = Bz * Sq;          // 2048 tokens
constexpr float EPS = 1e-5f;

// Scratch
__device__ float g_H1[T * H];
__device__ float g_Qb[T * H];
__device__ float g_Kb[T * H];
__device__ float g_Vb[T * H];
__device__ float g_mid[(size_t)T * FF];
__device__ int   g_perm[T];
__device__ int   g_rank[T];
__device__ int   g_cnt[NE];
__device__ int   g_off[NE];

// GEMM smem geometry: As[2][128][20], Bs[2][16][256] (XOR-swizzled)
constexpr int APITCH = 20;
constexpr int ABUF = 128 * APITCH;          // floats per A stage
constexpr int BBUF = 16 * 256;              // floats per B stage
constexpr int GEMM_SMEM = (2 * ABUF + 2 * BBUF) * 4;

// ---------------------------------------------------------------- PE add
__global__ void k_add_pe(const float* __restrict__ xin, float* __restrict__ x) {
    int idx = blockIdx.x * blockDim.x + threadIdx.x;
    if (idx >= T * H) return;
    int d = idx % H;
    int s = (idx / H) % Sq;
    int i2 = d & ~1;
    float div = expf(-(float)i2 * (9.210340371976184f / (float)H));
    float ang = (float)s * div;
    float pe = (d & 1) ? cosf(ang) : sinf(ang);
    x[idx] = xin[idx] + pe;
}

// ---------------------------------------------------------------- routing
__global__ void k_route(const int* __restrict__ ntp) {
    __shared__ int scnt[NE];
    __shared__ int soff[NE];
    int tid = threadIdx.x;
    if (tid < NE) scnt[tid] = 0;
    __syncthreads();
    for (int t = tid; t < T; t += blockDim.x) {
        int e = ntp[t];
        g_rank[t] = atomicAdd(&scnt[e], 1);
    }
    __syncthreads();
    if (tid == 0) {
        int a = 0;
        for (int e = 0; e < NE; e++) {
            soff[e] = a; g_off[e] = a; g_cnt[e] = scnt[e]; a += scnt[e];
        }
    }
    __syncthreads();
    for (int t = tid; t < T; t += blockDim.x) {
        int e = ntp[t];
        g_perm[soff[e] + g_rank[t]] = t;
    }
}

// ---------------------------------------------------------------- layernorm
__device__ __forceinline__ float block_sum_768(float v) {
    __shared__ float red[8];
    int tid = threadIdx.x;
    #pragma unroll
    for (int o = 16; o; o >>= 1) v += __shfl_xor_sync(0xffffffffu, v, o);
    if ((tid & 31) == 0) red[tid >> 5] = v;
    __syncthreads();
    float t = 0.f;
    if (tid < 32) {
        t = (tid < 8) ? red[tid] : 0.f;
        #pragma unroll
        for (int o = 4; o; o >>= 1) t += __shfl_xor_sync(0xffffffffu, t, o);
        if (tid == 0) red[0] = t;
    }
    __syncthreads();
    float r = red[0];
    __syncthreads();
    return r;
}

__global__ __launch_bounds__(256) void k_ln(const float* __restrict__ x,
                                            const float* __restrict__ w,
                                            const float* __restrict__ b) {
    int row = blockIdx.x;
    int tid = threadIdx.x;
    const float* xr = x + (size_t)row * H;
    float v0 = xr[tid], v1 = xr[tid + 256], v2 = xr[tid + 512];
    float mu = block_sum_768(v0 + v1 + v2) * (1.0f / H);
    float d0 = v0 - mu, d1 = v1 - mu, d2 = v2 - mu;
    float var = block_sum_768(d0 * d0 + d1 * d1 + d2 * d2) * (1.0f / H);
    float rstd = rsqrtf(var + EPS);
    float* orow = g_H1 + (size_t)row * H;
    orow[tid]       = d0 * rstd * w[tid]       + b[tid];
    orow[tid + 256] = d1 * rstd * w[tid + 256] + b[tid + 256];
    orow[tid + 512] = d2 * rstd * w[tid + 512] + b[tid + 512];
}

// ---------------------------------------------------------------- mma helpers
__device__ __forceinline__ uint32_t f2tf(float f) {
    uint32_t u;
    asm("cvt.rna.tf32.f32 %0, %1;" : "=r"(u) : "f"(f));
    return u;
}

__device__ __forceinline__ void mma_tf32(float (&c)[4], const uint32_t (&a)[4], const uint32_t (&b)[2]) {
    asm volatile(
        "mma.sync.aligned.m16n8k8.row.col.f32.tf32.tf32.f32 "
        "{%0,%1,%2,%3},{%4,%5,%6,%7},{%8,%9},{%0,%1,%2,%3};"
        : "+f"(c[0]), "+f"(c[1]), "+f"(c[2]), "+f"(c[3])
        : "r"(a[0]), "r"(a[1]), "r"(a[2]), "r"(a[3]), "r"(b[0]), "r"(b[1]));
}

__device__ __forceinline__ void cp16(void* s, const void* g, int pred) {
    uint32_t sa = (uint32_t)__cvta_generic_to_shared(s);
    asm volatile(
        "{\n\t.reg .pred p;\n\t"
        "setp.ne.b32 p, %2, 0;\n\t"
        ".reg .b32 sz;\n\t"
        "selp.b32 sz, 16, 0, p;\n\t"
        "cp.async.ca.shared.global [%0], [%1], 16, sz;\n\t}"
        :: "r"(sa), "l"(g), "r"(pred));
}

// ---------------------------------------------------------------- tf32 GEMM core
// Block tile 128x256, 256 threads / 8 warps (2x4), warp tile 64x64, BK=16, 2-stage.
// As: [128][20] fp32 row-major; Bs: [16][256], col swizzled: col' = col ^ ((k&3)*8).
__device__ __forceinline__ void gemm_mainloop(
    const float* __restrict__ Arow, int avalid,
    const float* __restrict__ Bg, int ldB, int Kdim, int n0,
    float (&c)[4][8][4], float* As, float* Bs)
{
    int tid = threadIdx.x;
    int lane = tid & 31, warp = tid >> 5;
    int grp = lane >> 2, qid = lane & 3;
    int wm = (warp & 1) * 64, wn = (warp >> 1) * 64;
    int q8 = qid * 8;

    int arow = tid >> 1, acv = (tid & 1) * 8;
    int bk = tid >> 4, bn = (tid & 15) * 16;
    int bsw = (bk & 3) * 8;
    int ntile = Kdim / 16;

    // B read columns (swizzled) for this thread
    int bcol[8];
    #pragma unroll
    for (int fn = 0; fn < 8; fn++) bcol[fn] = (wn + fn * 8 + grp) ^ q8;

    // prologue
    cp16(&As[arow * APITCH + acv],     Arow + acv,     avalid);
    cp16(&As[arow * APITCH + acv + 4], Arow + acv + 4, avalid);
    #pragma unroll
    for (int j = 0; j < 4; j++)
        cp16(&Bs[bk * 256 + ((bn + j * 4) ^ bsw)], Bg + (size_t)bk * ldB + n0 + bn + j * 4, 1);
    asm volatile("cp.async.commit_group;");

    for (int t = 0; t < ntile; t++) {
        int buf = t & 1;
        float* Ab = As + buf * ABUF;
        float* Bb = Bs + buf * BBUF;
        if (t + 1 < ntile) {
            int nbuf = buf ^ 1;
            int kt = (t + 1) * 16;
            cp16(&As[nbuf * ABUF + arow * APITCH + acv],     Arow + kt + acv,     avalid);
            cp16(&As[nbuf * ABUF + arow * APITCH + acv + 4], Arow + kt + acv + 4, avalid);
            #pragma unroll
            for (int j = 0; j < 4; j++)
                cp16(&Bs[nbuf * BBUF + bk * 256 + ((bn + j * 4) ^ bsw)],
                     Bg + (size_t)(kt + bk) * ldB + n0 + bn + j * 4, 1);
            asm volatile("cp.async.commit_group;");
            asm volatile("cp.async.wait_group 1;");
        } else {
            asm volatile("cp.async.wait_group 0;");
        }
        __syncthreads();

        #pragma unroll
        for (int k0 = 0; k0 < 16; k0 += 8) {
            uint32_t at[4][4];
            #pragma unroll
            for (int fm = 0; fm < 4; fm++) {
                int mm = wm + fm * 16 + grp;
                at[fm][0] = f2tf(Ab[(mm    ) * APITCH + k0 + qid]);
                at[fm][1] = f2tf(Ab[(mm + 8) * APITCH + k0 + qid]);
                at[fm][2] = f2tf(Ab[(mm    ) * APITCH + k0 + qid + 4]);
                at[fm][3] = f2tf(Ab[(mm + 8) * APITCH + k0 + qid + 4]);
            }
            uint32_t bt[8][2];
            #pragma unroll
            for (int fn = 0; fn < 8; fn++) {
                bt[fn][0] = f2tf(Bb[(k0 + qid    ) * 256 + bcol[fn]]);
                bt[fn][1] = f2tf(Bb[(k0 + qid + 4) * 256 + bcol[fn]]);
            }
            #pragma unroll
            for (int fm = 0; fm < 4; fm++)
                #pragma unroll
                for (int fn = 0; fn < 8; fn++)
                    mma_tf32(c[fm][fn], at[fm], bt[fn]);
        }
        __syncthreads();
    }
}

// ---------------------------------------------------------------- QKV GEMM
__global__ __launch_bounds__(256, 1) void k_qkv_tc(
    const float* __restrict__ Wq, const float* __restrict__ Wk, const float* __restrict__ Wv,
    const float* __restrict__ bq, const float* __restrict__ bk_, const float* __restrict__ bv)
{
    extern __shared__ float smbuf[];
    float* As = smbuf;
    float* Bs = smbuf + 2 * ABUF;
    const float* Bg; const float* bias; float* C;
    if (blockIdx.z == 0)      { Bg = Wq; bias = bq;  C = g_Qb; }
    else if (blockIdx.z == 1) { Bg = Wk; bias = bk_; C = g_Kb; }
    else                      { Bg = Wv; bias = bv;  C = g_Vb; }
    int m0 = blockIdx.y * 128, n0 = blockIdx.x * 256;
    const float* Arow = g_H1 + (size_t)(m0 + (threadIdx.x >> 1)) * H;
    float c[4][8][4] = {};
    gemm_mainloop(Arow, 1, Bg, H, H, n0, c, As, Bs);

    int lane = threadIdx.x & 31, warp = threadIdx.x >> 5;
    int grp = lane >> 2, qid = lane & 3;
    int wm = (warp & 1) * 64, wn = (warp >> 1) * 64;
    #pragma unroll
    for (int fn = 0; fn < 8; fn++) {
        int col = n0 + wn + fn * 8 + qid * 2;
        float bx = bias[col], by = bias[col + 1];
        #pragma unroll
        for (int fm = 0; fm < 4; fm++) {
            int m = m0 + wm + fm * 16 + grp;
            *(float2*)&C[(size_t)m * H + col]       = make_float2(c[fm][fn][0] + bx, c[fm][fn][1] + by);
            *(float2*)&C[(size_t)(m + 8) * H + col] = make_float2(c[fm][fn][2] + bx, c[fm][fn][3] + by);
        }
    }
}

// ---------------------------------------------------------------- FFN GEMM1 (gather + gelu)
__device__ __forceinline__ float gelu_f(float v) {
    return 0.5f * v * (1.0f + erff(v * 0.70710678118654752f));
}

__global__ __launch_bounds__(256, 1) void k_ffn1_tc(const float* __restrict__ W1l,
                                                    const float* __restrict__ b1l)
{
    extern __shared__ float smbuf[];
    float* As = smbuf;
    float* Bs = smbuf + 2 * ABUF;
    int e = blockIdx.z;
    int cnt = g_cnt[e];
    int m0 = blockIdx.y * 128;
    if (m0 >= cnt) return;
    int off = g_off[e];
    int n0 = blockIdx.x * 256;
    const float* Bg = W1l + (size_t)e * H * FF;
    const float* bias = b1l + (size_t)e * FF;

    int s = m0 + (threadIdx.x >> 1);
    int valid = (s < cnt);
    const float* Arow = g_H1 + (size_t)(valid ? g_perm[off + s] : 0) * H;
    float c[4][8][4] = {};
    gemm_mainloop(Arow, valid, Bg, FF, H, n0, c, As, Bs);

    int lane = threadIdx.x & 31, warp = threadIdx.x >> 5;
    int grp = lane >> 2, qid = lane & 3;
    int wm = (warp & 1) * 64, wn = (warp >> 1) * 64;
    #pragma unroll
    for (int fn = 0; fn < 8; fn++) {
        int col = n0 + wn + fn * 8 + qid * 2;
        float bx = bias[col], by = bias[col + 1];
        #pragma unroll
        for (int fm = 0; fm < 4; fm++) {
            int gm = m0 + wm + fm * 16 + grp;
            if (gm < cnt) {
                size_t r = (size_t)(off + gm) * FF + col;
                g_mid[r]     = gelu_f(c[fm][fn][0] + bx);
                g_mid[r + 1] = gelu_f(c[fm][fn][1] + by);
            }
            if (gm + 8 < cnt) {
                size_t r = (size_t)(off + gm + 8) * FF + col;
                g_mid[r]     = gelu_f(c[fm][fn][2] + bx);
                g_mid[r + 1] = gelu_f(c[fm][fn][3] + by);
            }
        }
    }
}

// ---------------------------------------------------------------- FFN GEMM2 (split-K=4, residual scatter)
constexpr int KSPLIT = 4;
constexpr int KCHUNK = FF / KSPLIT;   // 768

__global__ __launch_bounds__(256, 1) void k_ffn2_tc(const float* __restrict__ W2l,
                                                    const float* __restrict__ b2l,
                                                    float* __restrict__ x)
{
    extern __shared__ float smbuf[];
    float* As = smbuf;
    float* Bs = smbuf + 2 * ABUF;
    int e = blockIdx.z >> 2;
    int ks = blockIdx.z & 3;
    int cnt = g_cnt[e];
    int m0 = blockIdx.y * 128;
    if (m0 >= cnt) return;
    int off = g_off[e];
    int n0 = blockIdx.x * 256;
    int kbase = ks * KCHUNK;
    const float* Bg = W2l + (size_t)e * FF * H + (size_t)kbase * H;
    const float* bias = b2l + (size_t)e * H;

    int s = m0 + (threadIdx.x >> 1);
    int valid = (s < cnt);
    const float* Arow = g_mid + (size_t)(off + (valid ? s : m0)) * FF + kbase;
    float c[4][8][4] = {};
    gemm_mainloop(Arow, valid, Bg, H, KCHUNK, n0, c, As, Bs);

    int lane = threadIdx.x & 31, warp = threadIdx.x >> 5;
    int grp = lane >> 2, qid = lane & 3;
    int wm = (warp & 1) * 64, wn = (warp >> 1) * 64;

    int tok0[4], tok1[4];
    #pragma unroll
    for (int fm = 0; fm < 4; fm++) {
        int gm = m0 + wm + fm * 16 + grp;
        tok0[fm] = (gm < cnt)     ? g_perm[off + gm]     : -1;
        tok1[fm] = (gm + 8 < cnt) ? g_perm[off + gm + 8] : -1;
    }
    #pragma unroll
    for (int fn = 0; fn < 8; fn++) {
        int col = n0 + wn + fn * 8 + qid * 2;
        float bx = (ks == 0) ? bias[col]     : 0.f;
        float by = (ks == 0) ? bias[col + 1] : 0.f;
        #pragma unroll
        for (int fm = 0; fm < 4; fm++) {
            if (tok0[fm] >= 0) {
                float* p = &x[(size_t)tok0[fm] * H + col];
                atomicAdd(p,     c[fm][fn][0] + bx);
                atomicAdd(p + 1, c[fm][fn][1] + by);
            }
            if (tok1[fm] >= 0) {
                float* p = &x[(size_t)tok1[fm] * H + col];
                atomicAdd(p,     c[fm][fn][2] + bx);
                atomicAdd(p + 1, c[fm][fn][3] + by);
            }
        }
    }
}

// ---------------------------------------------------------------- attention (tensor cores)
constexpr int QPAD = 68, KPAD = 68, VPAD = 72, PPAD = 260;
constexpr int ATTN_SMEM = (64 * QPAD + 256 * KPAD + 256 * VPAD) * 4;

__global__ __launch_bounds__(128) void k_attn_tc(float* __restrict__ x) {
    extern __shared__ float sm[];
    float* Qs = sm;
    float* Ks = sm + 64 * QPAD;
    float* Vs = sm + 64 * QPAD + 256 * KPAD;
    float* Ps = Ks;
    int qt = blockIdx.x, hd = blockIdx.y, b = blockIdx.z;
    int tid = threadIdx.x;
    int lane = tid & 31, warp = tid >> 5;
    int grp = lane >> 2, qid = lane & 3;
    int hoff = hd * HD;
    int m = warp * 16;

    for (int v = tid; v < 64 * 16; v += 128) {
        int r = v >> 4, cv = (v & 15) * 4;
        float4 q4 = *(const float4*)(g_Qb + (size_t)(b * Sq + qt * 64 + r) * H + hoff + cv);
        Qs[r * QPAD + cv + 0] = q4.x; Qs[r * QPAD + cv + 1] = q4.y;
        Qs[r * QPAD + cv + 2] = q4.z; Qs[r * QPAD + cv + 3] = q4.w;
    }
    for (int v = tid; v < 256 * 16; v += 128) {
        int r = v >> 4, cv = (v & 15) * 4;
        float4 k4 = *(const float4*)(g_Kb + (size_t)(b * Sq + r) * H + hoff + cv);
        Ks[r * KPAD + cv + 0] = k4.x; Ks[r * KPAD + cv + 1] = k4.y;
        Ks[r * KPAD + cv + 2] = k4.z; Ks[r * KPAD + cv + 3] = k4.w;
        float4 v4 = *(const float4*)(g_Vb + (size_t)(b * Sq + r) * H + hoff + cv);
        Vs[r * VPAD + cv + 0] = v4.x; Vs[r * VPAD + cv + 1] = v4.y;
        Vs[r * VPAD + cv + 2] = v4.z; Vs[r * VPAD + cv + 3] = v4.w;
    }
    __syncthreads();

    float c[32][4];
    #pragma unroll
    for (int fn = 0; fn < 32; fn++)
        #pragma unroll
        for (int j = 0; j < 4; j++) c[fn][j] = 0.f;

    #pragma unroll
    for (int k0 = 0; k0 < 64; k0 += 8) {
        uint32_t at[4];
        at[0] = f2tf(Qs[(m + grp    ) * QPAD + k0 + qid]);
        at[1] = f2tf(Qs[(m + grp + 8) * QPAD + k0 + qid]);
        at[2] = f2tf(Qs[(m + grp    ) * QPAD + k0 + qid + 4]);
        at[3] = f2tf(Qs[(m + grp + 8) * QPAD + k0 + qid + 4]);
        #pragma unroll
        for (int fn = 0; fn < 32; fn++) {
            uint32_t bt[2];
            bt[0] = f2tf(Ks[(fn * 8 + grp) * KPAD + k0 + qid]);
            bt[1] = f2tf(Ks[(fn * 8 + grp) * KPAD + k0 + qid + 4]);
            mma_tf32(c[fn], at, bt);
        }
    }
    __syncthreads();

    float mx0 = -1e30f, mx1 = -1e30f;
    #pragma unroll
    for (int fn = 0; fn < 32; fn++) {
        mx0 = fmaxf(mx0, fmaxf(c[fn][0], c[fn][1]));
        mx1 = fmaxf(mx1, fmaxf(c[fn][2], c[fn][3]));
    }
    #pragma unroll
    for (int o = 1; o <= 2; o <<= 1) {
        mx0 = fmaxf(mx0, __shfl_xor_sync(0xffffffffu, mx0, o));
        mx1 = fmaxf(mx1, __shfl_xor_sync(0xffffffffu, mx1, o));
    }
    float s0 = 0.f, s1 = 0.f;
    #pragma unroll
    for (int fn = 0; fn < 32; fn++) {
        c[fn][0] = __expf(c[fn][0] - mx0); s0 += c[fn][0];
        c[fn][1] = __expf(c[fn][1] - mx0); s0 += c[fn][1];
        c[fn][2] = __expf(c[fn][2] - mx1); s1 += c[fn][2];
        c[fn][3] = __expf(c[fn][3] - mx1); s1 += c[fn][3];
    }
    #pragma unroll
    for (int o = 1; o <= 2; o <<= 1) {
        s0 += __shfl_xor_sync(0xffffffffu, s0, o);
        s1 += __shfl_xor_sync(0xffffffffu, s1, o);
    }
    float inv0 = 1.f / s0, inv1 = 1.f / s1;
    #pragma unroll
    for (int fn = 0; fn < 32; fn++) {
        int col = fn * 8 + qid * 2;
        *(float2*)&Ps[(m + grp    ) * PPAD + col] = make_float2(c[fn][0] * inv0, c[fn][1] * inv0);
        *(float2*)&Ps[(m + grp + 8) * PPAD + col] = make_float2(c[fn][2] * inv1, c[fn][3] * inv1);
    }
    __syncthreads();

    float c2[8][4];
    #pragma unroll
    for (int fn = 0; fn < 8; fn++)
        #pragma unroll
        for (int j = 0; j < 4; j++) c2[fn][j] = 0.f;

    #pragma unroll 4
    for (int k0 = 0; k0 < 256; k0 += 8) {
        uint32_t at[4];
        at[0] = f2tf(Ps[(m + grp    ) * PPAD + k0 + qid]);
        at[1] = f2tf(Ps[(m + grp + 8) * PPAD + k0 + qid]);
        at[2] = f2tf(Ps[(m + grp    ) * PPAD + k0 + qid + 4]);
        at[3] = f2tf(Ps[(m + grp + 8) * PPAD + k0 + qid + 4]);
        #pragma unroll
        for (int fn = 0; fn < 8; fn++) {
            uint32_t bt[2];
            bt[0] = f2tf(Vs[(k0 + qid    ) * VPAD + fn * 8 + grp]);
            bt[1] = f2tf(Vs[(k0 + qid + 4) * VPAD + fn * 8 + grp]);
            mma_tf32(c2[fn], at, bt);
        }
    }

    #pragma unroll
    for (int fn = 0; fn < 8; fn++) {
        int col = hoff + fn * 8 + qid * 2;
        size_t r0 = (size_t)(b * Sq + qt * 64 + m + grp) * H + col;
        size_t r1 = r0 + (size_t)8 * H;
        float2 v0 = *(float2*)&x[r0];
        v0.x += c2[fn][0]; v0.y += c2[fn][1];
        *(float2*)&x[r0] = v0;
        float2 v1 = *(float2*)&x[r1];
        v1.x += c2[fn][2]; v1.y += c2[fn][3];
        *(float2*)&x[r1] = v1;
    }
}

// ---------------------------------------------------------------- launch
extern "C" void kernel_launch(void* const* d_in, const int* in_sizes, int n_in,
                              void* d_out, int out_size) {
    (void)in_sizes; (void)n_in; (void)out_size;
    const float* x_in  = (const float*)d_in[0];
    const int*   ntp   = (const int*)d_in[2];
    const float* Wq    = (const float*)d_in[3];
    const float* bq    = (const float*)d_in[4];
    const float* Wk    = (const float*)d_in[5];
    const float* bk    = (const float*)d_in[6];
    const float* Wv    = (const float*)d_in[7];
    const float* bv    = (const float*)d_in[8];
    const float* ln1w  = (const float*)d_in[9];
    const float* ln1b  = (const float*)d_in[10];
    const float* ln2w  = (const float*)d_in[11];
    const float* ln2b  = (const float*)d_in[12];
    const float* W1    = (const float*)d_in[13];
    const float* b1    = (const float*)d_in[14];
    const float* W2    = (const float*)d_in[15];
    const float* b2    = (const float*)d_in[16];
    float* x = (float*)d_out;

    cudaFuncSetAttribute(k_attn_tc, cudaFuncAttributeMaxDynamicSharedMemorySize, ATTN_SMEM);
    cudaFuncSetAttribute(k_qkv_tc,  cudaFuncAttributeMaxDynamicSharedMemorySize, GEMM_SMEM);
    cudaFuncSetAttribute(k_ffn1_tc, cudaFuncAttributeMaxDynamicSharedMemorySize, GEMM_SMEM);
    cudaFuncSetAttribute(k_ffn2_tc, cudaFuncAttributeMaxDynamicSharedMemorySize, GEMM_SMEM);

    k_add_pe<<<(T * H + 255) / 256, 256>>>(x_in, x);
    k_route<<<1, 256>>>(ntp);

    for (int l = 0; l < Lr; l++) {
        k_ln<<<T, 256>>>(x, ln1w + l * H, ln1b + l * H);
        k_qkv_tc<<<dim3(H / 256, T / 128, 3), 256, GEMM_SMEM>>>(
            Wq + (size_t)l * H * H, Wk + (size_t)l * H * H, Wv + (size_t)l * H * H,
            bq + l * H, bk + l * H, bv + l * H);
        k_attn_tc<<<dim3(Sq / 64, NH, Bz), 128, ATTN_SMEM>>>(x);
        k_ln<<<T, 256>>>(x, ln2w + l * H, ln2b + l * H);
        k_ffn1_tc<<<dim3(FF / 256, T / 128, NE), 256, GEMM_SMEM>>>(
            W1 + (size_t)l * NE * H * FF, b1 + (size_t)l * NE * FF);
        k_ffn2_tc<<<dim3(H / 256, T / 128, NE * KSPLIT), 256, GEMM_SMEM>>>(
            W2 + (size_t)l * NE * FF * H, b2 + (size_t)l * NE * H, x);
    }
}

// round 6
// speedup vs baseline: 4.5459x; 1.6823x over previous
#include <cuda_runtime.h>
#include <cuda_fp16.h>
#include <math.h>
#include <stdint.h>

// Problem constants
constexpr int Bz = 8, Sq = 256, H = 768, Lr = 2, NE = 4, FF = 3072;
constexpr int NH = 12, HD = 64;
constexpr int T = Bz * Sq;          // 2048 tokens
constexpr float EPS = 1e-5f;

// fp16 scratch
__device__ __half g_H1h[T * H];
__device__ __half g_Qh[T * H];
__device__ __half g_Kh[T * H];
__device__ __half g_Vh[T * H];
__device__ __half g_midh[(size_t)T * FF];
__device__ __half g_Wqh[Lr * H * H];
__device__ __half g_Wkh[Lr * H * H];
__device__ __half g_Wvh[Lr * H * H];
__device__ __half g_W1h[(size_t)Lr * NE * H * FF];
__device__ __half g_W2h[(size_t)Lr * NE * FF * H];
__device__ int   g_perm[T];
__device__ int   g_rank[T];
__device__ int   g_cnt[NE];
__device__ int   g_off[NE];

// GEMM smem geometry (bytes). Stage = BK=32 k-slice.
// A: 128 rows x 32 halves (64B data), pitch 80B. B: 32 rows x 256 halves,
// pitch 512B, 16B-unit XOR swizzle u' = u ^ (k&7).
constexpr int APITCHB = 80;
constexpr int ABUFB = 128 * APITCHB;     // 10240
constexpr int BBUFB = 32 * 512;          // 16384
constexpr int STAGEB = ABUFB + BBUFB;    // 26624
constexpr int GEMM_SMEM = 2 * STAGEB;    // 53248

// ---------------------------------------------------------------- fp32 -> fp16 convert
__global__ void k_f2h(const float* __restrict__ in, __half* __restrict__ out, int n) {
    int i = (blockIdx.x * blockDim.x + threadIdx.x) * 4;
    if (i >= n) return;
    float4 v = *(const float4*)(in + i);
    *(__half2*)(out + i)     = __floats2half2_rn(v.x, v.y);
    *(__half2*)(out + i + 2) = __floats2half2_rn(v.z, v.w);
}

// ---------------------------------------------------------------- PE add
__global__ void k_add_pe(const float* __restrict__ xin, float* __restrict__ x) {
    int idx = blockIdx.x * blockDim.x + threadIdx.x;
    if (idx >= T * H) return;
    int d = idx % H;
    int s = (idx / H) % Sq;
    int i2 = d & ~1;
    float div = expf(-(float)i2 * (9.210340371976184f / (float)H));
    float ang = (float)s * div;
    float pe = (d & 1) ? cosf(ang) : sinf(ang);
    x[idx] = xin[idx] + pe;
}

// ---------------------------------------------------------------- routing
__global__ void k_route(const int* __restrict__ ntp) {
    __shared__ int scnt[NE];
    __shared__ int soff[NE];
    int tid = threadIdx.x;
    if (tid < NE) scnt[tid] = 0;
    __syncthreads();
    for (int t = tid; t < T; t += blockDim.x) {
        int e = ntp[t];
        g_rank[t] = atomicAdd(&scnt[e], 1);
    }
    __syncthreads();
    if (tid == 0) {
        int a = 0;
        for (int e = 0; e < NE; e++) {
            soff[e] = a; g_off[e] = a; g_cnt[e] = scnt[e]; a += scnt[e];
        }
    }
    __syncthreads();
    for (int t = tid; t < T; t += blockDim.x) {
        int e = ntp[t];
        g_perm[soff[e] + g_rank[t]] = t;
    }
}

// ---------------------------------------------------------------- layernorm (fp16 out)
__device__ __forceinline__ float block_sum_768(float v) {
    __shared__ float red[8];
    int tid = threadIdx.x;
    #pragma unroll
    for (int o = 16; o; o >>= 1) v += __shfl_xor_sync(0xffffffffu, v, o);
    if ((tid & 31) == 0) red[tid >> 5] = v;
    __syncthreads();
    float t = 0.f;
    if (tid < 32) {
        t = (tid < 8) ? red[tid] : 0.f;
        #pragma unroll
        for (int o = 4; o; o >>= 1) t += __shfl_xor_sync(0xffffffffu, t, o);
        if (tid == 0) red[0] = t;
    }
    __syncthreads();
    float r = red[0];
    __syncthreads();
    return r;
}

__global__ __launch_bounds__(256) void k_ln(const float* __restrict__ x,
                                            const float* __restrict__ w,
                                            const float* __restrict__ b) {
    int row = blockIdx.x;
    int tid = threadIdx.x;
    const float* xr = x + (size_t)row * H;
    float v0 = xr[tid], v1 = xr[tid + 256], v2 = xr[tid + 512];
    float mu = block_sum_768(v0 + v1 + v2) * (1.0f / H);
    float d0 = v0 - mu, d1 = v1 - mu, d2 = v2 - mu;
    float var = block_sum_768(d0 * d0 + d1 * d1 + d2 * d2) * (1.0f / H);
    float rstd = rsqrtf(var + EPS);
    __half* orow = g_H1h + (size_t)row * H;
    orow[tid]       = __float2half(d0 * rstd * w[tid]       + b[tid]);
    orow[tid + 256] = __float2half(d1 * rstd * w[tid + 256] + b[tid + 256]);
    orow[tid + 512] = __float2half(d2 * rstd * w[tid + 512] + b[tid + 512]);
}

// ---------------------------------------------------------------- mma / ldsm helpers
__device__ __forceinline__ uint32_t s2u(const void* p) {
    return (uint32_t)__cvta_generic_to_shared(p);
}

__device__ __forceinline__ void ldsm_x4(uint32_t (&r)[4], uint32_t addr) {
    asm volatile("ldmatrix.sync.aligned.m8n8.x4.shared.b16 {%0,%1,%2,%3}, [%4];"
        : "=r"(r[0]), "=r"(r[1]), "=r"(r[2]), "=r"(r[3]) : "r"(addr));
}

__device__ __forceinline__ void ldsm_x4_t(uint32_t (&r)[4], uint32_t addr) {
    asm volatile("ldmatrix.sync.aligned.m8n8.x4.trans.shared.b16 {%0,%1,%2,%3}, [%4];"
        : "=r"(r[0]), "=r"(r[1]), "=r"(r[2]), "=r"(r[3]) : "r"(addr));
}

__device__ __forceinline__ void mma_f16(float (&c)[4], const uint32_t (&a)[4], const uint32_t (&b)[2]) {
    asm volatile(
        "mma.sync.aligned.m16n8k16.row.col.f32.f16.f16.f32 "
        "{%0,%1,%2,%3},{%4,%5,%6,%7},{%8,%9},{%0,%1,%2,%3};"
        : "+f"(c[0]), "+f"(c[1]), "+f"(c[2]), "+f"(c[3])
        : "r"(a[0]), "r"(a[1]), "r"(a[2]), "r"(a[3]), "r"(b[0]), "r"(b[1]));
}

__device__ __forceinline__ uint32_t f2tf(float f) {
    uint32_t u;
    asm("cvt.rna.tf32.f32 %0, %1;" : "=r"(u) : "f"(f));
    return u;
}

__device__ __forceinline__ void mma_tf32(float (&c)[4], const uint32_t (&a)[4], const uint32_t (&b)[2]) {
    asm volatile(
        "mma.sync.aligned.m16n8k8.row.col.f32.tf32.tf32.f32 "
        "{%0,%1,%2,%3},{%4,%5,%6,%7},{%8,%9},{%0,%1,%2,%3};"
        : "+f"(c[0]), "+f"(c[1]), "+f"(c[2]), "+f"(c[3])
        : "r"(a[0]), "r"(a[1]), "r"(a[2]), "r"(a[3]), "r"(b[0]), "r"(b[1]));
}

__device__ __forceinline__ void cp16(void* s, const void* g, int pred) {
    uint32_t sa = s2u(s);
    asm volatile(
        "{\n\t.reg .pred p;\n\t"
        "setp.ne.b32 p, %2, 0;\n\t"
        ".reg .b32 sz;\n\t"
        "selp.b32 sz, 16, 0, p;\n\t"
        "cp.async.ca.shared.global [%0], [%1], 16, sz;\n\t}"
        :: "r"(sa), "l"(g), "r"(pred));
}

// ---------------------------------------------------------------- fp16 GEMM core
// Block tile 128x256, 256 thr / 8 warps (2x4), warp tile 64x64, BK=32, 2-stage cp.async.
__device__ __forceinline__ void gemm_mainloop_h(
    const __half* __restrict__ Arow, int avalid,
    const __half* __restrict__ Bg, int ldB, int Kdim, int n0,
    float (&c)[4][8][4], char* sm)
{
    int tid = threadIdx.x;
    int lane = tid & 31, warp = tid >> 5;
    int wm = (warp & 1) * 64, wn = (warp >> 1) * 64;

    int arow = tid >> 1;
    int ah0 = (tid & 1) * 2;
    int ntile = Kdim / 32;

    char* As0 = sm;
    char* Bs0 = sm + ABUFB;

    // prologue stage 0
    {
        const __half* ag = Arow + ah0 * 8;
        cp16(As0 + arow * APITCHB + ah0 * 16,       ag,     avalid);
        cp16(As0 + arow * APITCHB + (ah0 + 1) * 16, ag + 8, avalid);
        #pragma unroll
        for (int j = 0; j < 4; j++) {
            int cc = tid * 4 + j;
            int k = cc >> 5, u = cc & 31;
            cp16(Bs0 + k * 512 + ((u ^ (k & 7)) * 16), Bg + (size_t)k * ldB + n0 + u * 8, 1);
        }
    }
    asm volatile("cp.async.commit_group;");

    for (int t = 0; t < ntile; t++) {
        int buf = t & 1;
        char* Ab = sm + buf * STAGEB;
        char* Bb = sm + buf * STAGEB + ABUFB;
        if (t + 1 < ntile) {
            char* An = sm + (buf ^ 1) * STAGEB;
            char* Bn = sm + (buf ^ 1) * STAGEB + ABUFB;
            int kt = (t + 1) * 32;
            const __half* ag = Arow + kt + ah0 * 8;
            cp16(An + arow * APITCHB + ah0 * 16,       ag,     avalid);
            cp16(An + arow * APITCHB + (ah0 + 1) * 16, ag + 8, avalid);
            #pragma unroll
            for (int j = 0; j < 4; j++) {
                int cc = tid * 4 + j;
                int k = cc >> 5, u = cc & 31;
                cp16(Bn + k * 512 + ((u ^ (k & 7)) * 16),
                     Bg + (size_t)(kt + k) * ldB + n0 + u * 8, 1);
            }
            asm volatile("cp.async.commit_group;");
            asm volatile("cp.async.wait_group 1;");
        } else {
            asm volatile("cp.async.wait_group 0;");
        }
        __syncthreads();

        #pragma unroll
        for (int s16 = 0; s16 < 2; s16++) {
            uint32_t a[4][4];
            #pragma unroll
            for (int fm = 0; fm < 4; fm++) {
                int r = wm + fm * 16 + (lane & 15);
                uint32_t addr = s2u(Ab + r * APITCHB + (s16 * 2 + (lane >> 4)) * 16);
                ldsm_x4(a[fm], addr);
            }
            uint32_t b[8][2];
            #pragma unroll
            for (int fnp = 0; fnp < 4; fnp++) {
                int k = s16 * 16 + (lane & 7) + ((lane >> 3) & 1) * 8;
                int u = ((wn + fnp * 16) >> 3) + (lane >> 4);
                uint32_t addr = s2u(Bb + k * 512 + ((u ^ (k & 7)) * 16));
                uint32_t r4[4];
                ldsm_x4_t(r4, addr);
                b[2 * fnp][0] = r4[0]; b[2 * fnp][1] = r4[1];
                b[2 * fnp + 1][0] = r4[2]; b[2 * fnp + 1][1] = r4[3];
            }
            #pragma unroll
            for (int fm = 0; fm < 4; fm++)
                #pragma unroll
                for (int fn = 0; fn < 8; fn++)
                    mma_f16(c[fm][fn], a[fm], b[fn]);
        }
        __syncthreads();
    }
}

// ---------------------------------------------------------------- QKV GEMM (fp16)
__global__ __launch_bounds__(256, 1) void k_qkv_tc(
    int l, const float* __restrict__ bq, const float* __restrict__ bk_, const float* __restrict__ bv)
{
    extern __shared__ char smbuf[];
    const __half* Bg; const float* bias; __half* C;
    if (blockIdx.z == 0)      { Bg = g_Wqh + (size_t)l * H * H; bias = bq;  C = g_Qh; }
    else if (blockIdx.z == 1) { Bg = g_Wkh + (size_t)l * H * H; bias = bk_; C = g_Kh; }
    else                      { Bg = g_Wvh + (size_t)l * H * H; bias = bv;  C = g_Vh; }
    int m0 = blockIdx.y * 128, n0 = blockIdx.x * 256;
    const __half* Arow = g_H1h + (size_t)(m0 + (threadIdx.x >> 1)) * H;
    float c[4][8][4] = {};
    gemm_mainloop_h(Arow, 1, Bg, H, H, n0, c, smbuf);

    int lane = threadIdx.x & 31, warp = threadIdx.x >> 5;
    int grp = lane >> 2, qid = lane & 3;
    int wm = (warp & 1) * 64, wn = (warp >> 1) * 64;
    #pragma unroll
    for (int fn = 0; fn < 8; fn++) {
        int col = n0 + wn + fn * 8 + qid * 2;
        float bx = bias[col], by = bias[col + 1];
        #pragma unroll
        for (int fm = 0; fm < 4; fm++) {
            int m = m0 + wm + fm * 16 + grp;
            *(__half2*)&C[(size_t)m * H + col]       = __floats2half2_rn(c[fm][fn][0] + bx, c[fm][fn][1] + by);
            *(__half2*)&C[(size_t)(m + 8) * H + col] = __floats2half2_rn(c[fm][fn][2] + bx, c[fm][fn][3] + by);
        }
    }
}

// ---------------------------------------------------------------- FFN GEMM1 (gather + gelu, fp16)
__device__ __forceinline__ float gelu_f(float v) {
    return 0.5f * v * (1.0f + erff(v * 0.70710678118654752f));
}

__global__ __launch_bounds__(256, 1) void k_ffn1_tc(int l, const float* __restrict__ b1l)
{
    extern __shared__ char smbuf[];
    int e = blockIdx.z;
    int cnt = g_cnt[e];
    int m0 = blockIdx.y * 128;
    if (m0 >= cnt) return;
    int off = g_off[e];
    int n0 = blockIdx.x * 256;
    const __half* Bg = g_W1h + ((size_t)l * NE + e) * H * FF;   // device-side symbol arithmetic
    const float* bias = b1l + (size_t)e * FF;

    int s = m0 + (threadIdx.x >> 1);
    int valid = (s < cnt);
    const __half* Arow = g_H1h + (size_t)(valid ? g_perm[off + s] : 0) * H;
    float c[4][8][4] = {};
    gemm_mainloop_h(Arow, valid, Bg, FF, H, n0, c, smbuf);

    int lane = threadIdx.x & 31, warp = threadIdx.x >> 5;
    int grp = lane >> 2, qid = lane & 3;
    int wm = (warp & 1) * 64, wn = (warp >> 1) * 64;
    #pragma unroll
    for (int fn = 0; fn < 8; fn++) {
        int col = n0 + wn + fn * 8 + qid * 2;
        float bx = bias[col], by = bias[col + 1];
        #pragma unroll
        for (int fm = 0; fm < 4; fm++) {
            int gm = m0 + wm + fm * 16 + grp;
            if (gm < cnt) {
                size_t r = (size_t)(off + gm) * FF + col;
                *(__half2*)&g_midh[r] = __floats2half2_rn(gelu_f(c[fm][fn][0] + bx), gelu_f(c[fm][fn][1] + by));
            }
            if (gm + 8 < cnt) {
                size_t r = (size_t)(off + gm + 8) * FF + col;
                *(__half2*)&g_midh[r] = __floats2half2_rn(gelu_f(c[fm][fn][2] + bx), gelu_f(c[fm][fn][3] + by));
            }
        }
    }
}

// ---------------------------------------------------------------- FFN GEMM2 (split-K=4, residual scatter)
constexpr int KSPLIT = 4;
constexpr int KCHUNK = FF / KSPLIT;   // 768

__global__ __launch_bounds__(256, 1) void k_ffn2_tc(int l, const float* __restrict__ b2l,
                                                    float* __restrict__ x)
{
    extern __shared__ char smbuf[];
    int e = blockIdx.z >> 2;
    int ks = blockIdx.z & 3;
    int cnt = g_cnt[e];
    int m0 = blockIdx.y * 128;
    if (m0 >= cnt) return;
    int off = g_off[e];
    int n0 = blockIdx.x * 256;
    int kbase = ks * KCHUNK;
    const __half* Bg = g_W2h + ((size_t)l * NE + e) * FF * H + (size_t)kbase * H;  // device-side
    const float* bias = b2l + (size_t)e * H;

    int s = m0 + (threadIdx.x >> 1);
    int valid = (s < cnt);
    const __half* Arow = g_midh + (size_t)(off + (valid ? s : m0)) * FF + kbase;
    float c[4][8][4] = {};
    gemm_mainloop_h(Arow, valid, Bg, H, KCHUNK, n0, c, smbuf);

    int lane = threadIdx.x & 31, warp = threadIdx.x >> 5;
    int grp = lane >> 2, qid = lane & 3;
    int wm = (warp & 1) * 64, wn = (warp >> 1) * 64;

    int tok0[4], tok1[4];
    #pragma unroll
    for (int fm = 0; fm < 4; fm++) {
        int gm = m0 + wm + fm * 16 + grp;
        tok0[fm] = (gm < cnt)     ? g_perm[off + gm]     : -1;
        tok1[fm] = (gm + 8 < cnt) ? g_perm[off + gm + 8] : -1;
    }
    #pragma unroll
    for (int fn = 0; fn < 8; fn++) {
        int col = n0 + wn + fn * 8 + qid * 2;
        float bx = (ks == 0) ? bias[col]     : 0.f;
        float by = (ks == 0) ? bias[col + 1] : 0.f;
        #pragma unroll
        for (int fm = 0; fm < 4; fm++) {
            if (tok0[fm] >= 0) {
                float* p = &x[(size_t)tok0[fm] * H + col];
                atomicAdd(p,     c[fm][fn][0] + bx);
                atomicAdd(p + 1, c[fm][fn][1] + by);
            }
            if (tok1[fm] >= 0) {
                float* p = &x[(size_t)tok1[fm] * H + col];
                atomicAdd(p,     c[fm][fn][2] + bx);
                atomicAdd(p + 1, c[fm][fn][3] + by);
            }
        }
    }
}

// ---------------------------------------------------------------- attention (tf32 mma; fp16 source)
constexpr int QPAD = 68, KPAD = 68, VPAD = 72, PPAD = 260;
constexpr int ATTN_SMEM = (64 * QPAD + 256 * KPAD + 256 * VPAD) * 4;

__global__ __launch_bounds__(128) void k_attn_tc(float* __restrict__ x) {
    extern __shared__ float sm[];
    float* Qs = sm;
    float* Ks = sm + 64 * QPAD;
    float* Vs = sm + 64 * QPAD + 256 * KPAD;
    float* Ps = Ks;
    int qt = blockIdx.x, hd = blockIdx.y, b = blockIdx.z;
    int tid = threadIdx.x;
    int lane = tid & 31, warp = tid >> 5;
    int grp = lane >> 2, qid = lane & 3;
    int hoff = hd * HD;
    int m = warp * 16;

    for (int v = tid; v < 64 * 16; v += 128) {
        int r = v >> 4, cv = (v & 15) * 4;
        const __half* gp = g_Qh + (size_t)(b * Sq + qt * 64 + r) * H + hoff + cv;
        float2 f01 = __half22float2(*(const __half2*)gp);
        float2 f23 = __half22float2(*(const __half2*)(gp + 2));
        Qs[r * QPAD + cv + 0] = f01.x; Qs[r * QPAD + cv + 1] = f01.y;
        Qs[r * QPAD + cv + 2] = f23.x; Qs[r * QPAD + cv + 3] = f23.y;
    }
    for (int v = tid; v < 256 * 16; v += 128) {
        int r = v >> 4, cv = (v & 15) * 4;
        const __half* kp = g_Kh + (size_t)(b * Sq + r) * H + hoff + cv;
        float2 k01 = __half22float2(*(const __half2*)kp);
        float2 k23 = __half22float2(*(const __half2*)(kp + 2));
        Ks[r * KPAD + cv + 0] = k01.x; Ks[r * KPAD + cv + 1] = k01.y;
        Ks[r * KPAD + cv + 2] = k23.x; Ks[r * KPAD + cv + 3] = k23.y;
        const __half* vp = g_Vh + (size_t)(b * Sq + r) * H + hoff + cv;
        float2 v01 = __half22float2(*(const __half2*)vp);
        float2 v23 = __half22float2(*(const __half2*)(vp + 2));
        Vs[r * VPAD + cv + 0] = v01.x; Vs[r * VPAD + cv + 1] = v01.y;
        Vs[r * VPAD + cv + 2] = v23.x; Vs[r * VPAD + cv + 3] = v23.y;
    }
    __syncthreads();

    float c[32][4];
    #pragma unroll
    for (int fn = 0; fn < 32; fn++)
        #pragma unroll
        for (int j = 0; j < 4; j++) c[fn][j] = 0.f;

    #pragma unroll
    for (int k0 = 0; k0 < 64; k0 += 8) {
        uint32_t at[4];
        at[0] = f2tf(Qs[(m + grp    ) * QPAD + k0 + qid]);
        at[1] = f2tf(Qs[(m + grp + 8) * QPAD + k0 + qid]);
        at[2] = f2tf(Qs[(m + grp    ) * QPAD + k0 + qid + 4]);
        at[3] = f2tf(Qs[(m + grp + 8) * QPAD + k0 + qid + 4]);
        #pragma unroll
        for (int fn = 0; fn < 32; fn++) {
            uint32_t bt[2];
            bt[0] = f2tf(Ks[(fn * 8 + grp) * KPAD + k0 + qid]);
            bt[1] = f2tf(Ks[(fn * 8 + grp) * KPAD + k0 + qid + 4]);
            mma_tf32(c[fn], at, bt);
        }
    }
    __syncthreads();

    float mx0 = -1e30f, mx1 = -1e30f;
    #pragma unroll
    for (int fn = 0; fn < 32; fn++) {
        mx0 = fmaxf(mx0, fmaxf(c[fn][0], c[fn][1]));
        mx1 = fmaxf(mx1, fmaxf(c[fn][2], c[fn][3]));
    }
    #pragma unroll
    for (int o = 1; o <= 2; o <<= 1) {
        mx0 = fmaxf(mx0, __shfl_xor_sync(0xffffffffu, mx0, o));
        mx1 = fmaxf(mx1, __shfl_xor_sync(0xffffffffu, mx1, o));
    }
    float s0 = 0.f, s1 = 0.f;
    #pragma unroll
    for (int fn = 0; fn < 32; fn++) {
        c[fn][0] = __expf(c[fn][0] - mx0); s0 += c[fn][0];
        c[fn][1] = __expf(c[fn][1] - mx0); s0 += c[fn][1];
        c[fn][2] = __expf(c[fn][2] - mx1); s1 += c[fn][2];
        c[fn][3] = __expf(c[fn][3] - mx1); s1 += c[fn][3];
    }
    #pragma unroll
    for (int o = 1; o <= 2; o <<= 1) {
        s0 += __shfl_xor_sync(0xffffffffu, s0, o);
        s1 += __shfl_xor_sync(0xffffffffu, s1, o);
    }
    float inv0 = 1.f / s0, inv1 = 1.f / s1;
    #pragma unroll
    for (int fn = 0; fn < 32; fn++) {
        int col = fn * 8 + qid * 2;
        *(float2*)&Ps[(m + grp    ) * PPAD + col] = make_float2(c[fn][0] * inv0, c[fn][1] * inv0);
        *(float2*)&Ps[(m + grp + 8) * PPAD + col] = make_float2(c[fn][2] * inv1, c[fn][3] * inv1);
    }
    __syncthreads();

    float c2[8][4];
    #pragma unroll
    for (int fn = 0; fn < 8; fn++)
        #pragma unroll
        for (int j = 0; j < 4; j++) c2[fn][j] = 0.f;

    #pragma unroll 4
    for (int k0 = 0; k0 < 256; k0 += 8) {
        uint32_t at[4];
        at[0] = f2tf(Ps[(m + grp    ) * PPAD + k0 + qid]);
        at[1] = f2tf(Ps[(m + grp + 8) * PPAD + k0 + qid]);
        at[2] = f2tf(Ps[(m + grp    ) * PPAD + k0 + qid + 4]);
        at[3] = f2tf(Ps[(m + grp + 8) * PPAD + k0 + qid + 4]);
        #pragma unroll
        for (int fn = 0; fn < 8; fn++) {
            uint32_t bt[2];
            bt[0] = f2tf(Vs[(k0 + qid    ) * VPAD + fn * 8 + grp]);
            bt[1] = f2tf(Vs[(k0 + qid + 4) * VPAD + fn * 8 + grp]);
            mma_tf32(c2[fn], at, bt);
        }
    }

    #pragma unroll
    for (int fn = 0; fn < 8; fn++) {
        int col = hoff + fn * 8 + qid * 2;
        size_t r0 = (size_t)(b * Sq + qt * 64 + m + grp) * H + col;
        size_t r1 = r0 + (size_t)8 * H;
        float2 v0 = *(float2*)&x[r0];
        v0.x += c2[fn][0]; v0.y += c2[fn][1];
        *(float2*)&x[r0] = v0;
        float2 v1 = *(float2*)&x[r1];
        v1.x += c2[fn][2]; v1.y += c2[fn][3];
        *(float2*)&x[r1] = v1;
    }
}

// ---------------------------------------------------------------- launch
extern "C" void kernel_launch(void* const* d_in, const int* in_sizes, int n_in,
                              void* d_out, int out_size) {
    (void)in_sizes; (void)n_in; (void)out_size;
    const float* x_in  = (const float*)d_in[0];
    const int*   ntp   = (const int*)d_in[2];
    const float* Wq    = (const float*)d_in[3];
    const float* bq    = (const float*)d_in[4];
    const float* Wk    = (const float*)d_in[5];
    const float* bk    = (const float*)d_in[6];
    const float* Wv    = (const float*)d_in[7];
    const float* bv    = (const float*)d_in[8];
    const float* ln1w  = (const float*)d_in[9];
    const float* ln1b  = (const float*)d_in[10];
    const float* ln2w  = (const float*)d_in[11];
    const float* ln2b  = (const float*)d_in[12];
    const float* W1    = (const float*)d_in[13];
    const float* b1    = (const float*)d_in[14];
    const float* W2    = (const float*)d_in[15];
    const float* b2    = (const float*)d_in[16];
    float* x = (float*)d_out;

    cudaFuncSetAttribute(k_attn_tc, cudaFuncAttributeMaxDynamicSharedMemorySize, ATTN_SMEM);
    cudaFuncSetAttribute(k_qkv_tc,  cudaFuncAttributeMaxDynamicSharedMemorySize, GEMM_SMEM);
    cudaFuncSetAttribute(k_ffn1_tc, cudaFuncAttributeMaxDynamicSharedMemorySize, GEMM_SMEM);
    cudaFuncSetAttribute(k_ffn2_tc, cudaFuncAttributeMaxDynamicSharedMemorySize, GEMM_SMEM);

    // weight conversion (fp32 -> fp16); device addresses via cudaGetSymbolAddress (correct API)
    {
        __half* dWq; cudaGetSymbolAddress((void**)&dWq, g_Wqh);
        __half* dWk; cudaGetSymbolAddress((void**)&dWk, g_Wkh);
        __half* dWv; cudaGetSymbolAddress((void**)&dWv, g_Wvh);
        __half* dW1; cudaGetSymbolAddress((void**)&dW1, g_W1h);
        __half* dW2; cudaGetSymbolAddress((void**)&dW2, g_W2h);
        int nqkv = Lr * H * H;
        int nff  = Lr * NE * H * FF;
        k_f2h<<<(nqkv / 4 + 255) / 256, 256>>>(Wq, dWq, nqkv);
        k_f2h<<<(nqkv / 4 + 255) / 256, 256>>>(Wk, dWk, nqkv);
        k_f2h<<<(nqkv / 4 + 255) / 256, 256>>>(Wv, dWv, nqkv);
        k_f2h<<<(nff / 4 + 255) / 256, 256>>>(W1, dW1, nff);
        k_f2h<<<(nff / 4 + 255) / 256, 256>>>(W2, dW2, nff);
    }

    k_add_pe<<<(T * H + 255) / 256, 256>>>(x_in, x);
    k_route<<<1, 256>>>(ntp);

    for (int l = 0; l < Lr; l++) {
        k_ln<<<T, 256>>>(x, ln1w + l * H, ln1b + l * H);
        k_qkv_tc<<<dim3(H / 256, T / 128, 3), 256, GEMM_SMEM>>>(
            l, bq + l * H, bk + l * H, bv + l * H);
        k_attn_tc<<<dim3(Sq / 64, NH, Bz), 128, ATTN_SMEM>>>(x);
        k_ln<<<T, 256>>>(x, ln2w + l * H, ln2b + l * H);
        k_ffn1_tc<<<dim3(FF / 256, T / 128, NE), 256, GEMM_SMEM>>>(
            l, b1 + (size_t)l * NE * FF);
        k_ffn2_tc<<<dim3(H / 256, T / 128, NE * KSPLIT), 256, GEMM_SMEM>>>(
            l, b2 + (size_t)l * NE * H, x);
    }
}

// round 7
// speedup vs baseline: 5.1771x; 1.1388x over previous
#include <cuda_runtime.h>
#include <cuda_fp16.h>
#include <math.h>
#include <stdint.h>

// Problem constants
constexpr int Bz = 8, Sq = 256, H = 768, Lr = 2, NE = 4, FF = 3072;
constexpr int NH = 12, HD = 64;
constexpr int T = Bz * Sq;          // 2048 tokens
constexpr float EPS = 1e-5f;

// fp16 scratch
__device__ __half g_H1h[T * H];
__device__ __half g_Qh[T * H];
__device__ __half g_Kh[T * H];
__device__ __half g_Vh[T * H];
__device__ __half g_midh[(size_t)T * FF];
__device__ __half g_Wqh[Lr * H * H];
__device__ __half g_Wkh[Lr * H * H];
__device__ __half g_Wvh[Lr * H * H];
__device__ __half g_W1h[(size_t)Lr * NE * H * FF];
__device__ __half g_W2h[(size_t)Lr * NE * FF * H];
__device__ int   g_perm[T];
__device__ int   g_rank[T];
__device__ int   g_cnt[NE];
__device__ int   g_off[NE];

// GEMM smem geometry (bytes). Stage = BK=32 k-slice. 3 stages.
constexpr int APITCHB = 80;
constexpr int ABUFB = 128 * APITCHB;     // 10240
constexpr int BBUFB = 32 * 512;          // 16384
constexpr int STAGEB = ABUFB + BBUFB;    // 26624
constexpr int GEMM_SMEM = 3 * STAGEB;    // 79872

// ---------------------------------------------------------------- fp32 -> fp16 convert
__global__ void k_f2h(const float* __restrict__ in, __half* __restrict__ out, int n) {
    int i = (blockIdx.x * blockDim.x + threadIdx.x) * 4;
    if (i >= n) return;
    float4 v = *(const float4*)(in + i);
    *(__half2*)(out + i)     = __floats2half2_rn(v.x, v.y);
    *(__half2*)(out + i + 2) = __floats2half2_rn(v.z, v.w);
}

// ---------------------------------------------------------------- PE add
__global__ void k_add_pe(const float* __restrict__ xin, float* __restrict__ x) {
    int idx = blockIdx.x * blockDim.x + threadIdx.x;
    if (idx >= T * H) return;
    int d = idx % H;
    int s = (idx / H) % Sq;
    int i2 = d & ~1;
    float div = expf(-(float)i2 * (9.210340371976184f / (float)H));
    float ang = (float)s * div;
    float pe = (d & 1) ? cosf(ang) : sinf(ang);
    x[idx] = xin[idx] + pe;
}

// ---------------------------------------------------------------- routing
__global__ void k_route(const int* __restrict__ ntp) {
    __shared__ int scnt[NE];
    __shared__ int soff[NE];
    int tid = threadIdx.x;
    if (tid < NE) scnt[tid] = 0;
    __syncthreads();
    for (int t = tid; t < T; t += blockDim.x) {
        int e = ntp[t];
        g_rank[t] = atomicAdd(&scnt[e], 1);
    }
    __syncthreads();
    if (tid == 0) {
        int a = 0;
        for (int e = 0; e < NE; e++) {
            soff[e] = a; g_off[e] = a; g_cnt[e] = scnt[e]; a += scnt[e];
        }
    }
    __syncthreads();
    for (int t = tid; t < T; t += blockDim.x) {
        int e = ntp[t];
        g_perm[soff[e] + g_rank[t]] = t;
    }
}

// ---------------------------------------------------------------- layernorm (fp16 out)
__device__ __forceinline__ float block_sum_768(float v) {
    __shared__ float red[8];
    int tid = threadIdx.x;
    #pragma unroll
    for (int o = 16; o; o >>= 1) v += __shfl_xor_sync(0xffffffffu, v, o);
    if ((tid & 31) == 0) red[tid >> 5] = v;
    __syncthreads();
    float t = 0.f;
    if (tid < 32) {
        t = (tid < 8) ? red[tid] : 0.f;
        #pragma unroll
        for (int o = 4; o; o >>= 1) t += __shfl_xor_sync(0xffffffffu, t, o);
        if (tid == 0) red[0] = t;
    }
    __syncthreads();
    float r = red[0];
    __syncthreads();
    return r;
}

__global__ __launch_bounds__(256) void k_ln(const float* __restrict__ x,
                                            const float* __restrict__ w,
                                            const float* __restrict__ b) {
    int row = blockIdx.x;
    int tid = threadIdx.x;
    const float* xr = x + (size_t)row * H;
    float v0 = xr[tid], v1 = xr[tid + 256], v2 = xr[tid + 512];
    float mu = block_sum_768(v0 + v1 + v2) * (1.0f / H);
    float d0 = v0 - mu, d1 = v1 - mu, d2 = v2 - mu;
    float var = block_sum_768(d0 * d0 + d1 * d1 + d2 * d2) * (1.0f / H);
    float rstd = rsqrtf(var + EPS);
    __half* orow = g_H1h + (size_t)row * H;
    orow[tid]       = __float2half(d0 * rstd * w[tid]       + b[tid]);
    orow[tid + 256] = __float2half(d1 * rstd * w[tid + 256] + b[tid + 256]);
    orow[tid + 512] = __float2half(d2 * rstd * w[tid + 512] + b[tid + 512]);
}

// ---------------------------------------------------------------- mma / ldsm helpers
__device__ __forceinline__ uint32_t s2u(const void* p) {
    return (uint32_t)__cvta_generic_to_shared(p);
}

__device__ __forceinline__ void ldsm_x4(uint32_t (&r)[4], uint32_t addr) {
    asm volatile("ldmatrix.sync.aligned.m8n8.x4.shared.b16 {%0,%1,%2,%3}, [%4];"
        : "=r"(r[0]), "=r"(r[1]), "=r"(r[2]), "=r"(r[3]) : "r"(addr));
}

__device__ __forceinline__ void ldsm_x4_t(uint32_t (&r)[4], uint32_t addr) {
    asm volatile("ldmatrix.sync.aligned.m8n8.x4.trans.shared.b16 {%0,%1,%2,%3}, [%4];"
        : "=r"(r[0]), "=r"(r[1]), "=r"(r[2]), "=r"(r[3]) : "r"(addr));
}

__device__ __forceinline__ void mma_f16(float (&c)[4], const uint32_t (&a)[4], uint32_t b0, uint32_t b1) {
    asm volatile(
        "mma.sync.aligned.m16n8k16.row.col.f32.f16.f16.f32 "
        "{%0,%1,%2,%3},{%4,%5,%6,%7},{%8,%9},{%0,%1,%2,%3};"
        : "+f"(c[0]), "+f"(c[1]), "+f"(c[2]), "+f"(c[3])
        : "r"(a[0]), "r"(a[1]), "r"(a[2]), "r"(a[3]), "r"(b0), "r"(b1));
}

__device__ __forceinline__ void cp16(void* s, const void* g, int pred) {
    uint32_t sa = s2u(s);
    asm volatile(
        "{\n\t.reg .pred p;\n\t"
        "setp.ne.b32 p, %2, 0;\n\t"
        ".reg .b32 sz;\n\t"
        "selp.b32 sz, 16, 0, p;\n\t"
        "cp.async.ca.shared.global [%0], [%1], 16, sz;\n\t}"
        :: "r"(sa), "l"(g), "r"(pred));
}

// ---------------------------------------------------------------- fp16 GEMM core
// Block tile 128x256, 256 thr / 8 warps (2x4), warp tile 64x64, BK=32, 3-stage cp.async,
// single __syncthreads per k-iteration.
__device__ __forceinline__ void gemm_mainloop_h(
    const __half* __restrict__ Arow, int avalid,
    const __half* __restrict__ Bg, int ldB, int Kdim, int n0,
    float (&c)[4][8][4], char* sm)
{
    int tid = threadIdx.x;
    int lane = tid & 31, warp = tid >> 5;
    int wm = (warp & 1) * 64, wn = (warp >> 1) * 64;

    int arow = tid >> 1;
    int ah0 = (tid & 1) * 2;
    int ntile = Kdim / 32;

    // stage loader
    auto load_stage = [&](int t, char* dst) {
        int kt = t * 32;
        char* As = dst;
        char* Bs = dst + ABUFB;
        const __half* ag = Arow + kt + ah0 * 8;
        cp16(As + arow * APITCHB + ah0 * 16,       ag,     avalid);
        cp16(As + arow * APITCHB + (ah0 + 1) * 16, ag + 8, avalid);
        #pragma unroll
        for (int j = 0; j < 4; j++) {
            int cc = tid * 4 + j;
            int k = cc >> 5, u = cc & 31;
            cp16(Bs + k * 512 + ((u ^ (k & 7)) * 16),
                 Bg + (size_t)(kt + k) * ldB + n0 + u * 8, 1);
        }
    };

    load_stage(0, sm);
    asm volatile("cp.async.commit_group;");
    if (ntile > 1) load_stage(1, sm + STAGEB);
    asm volatile("cp.async.commit_group;");

    for (int t = 0; t < ntile; t++) {
        asm volatile("cp.async.wait_group 1;");
        __syncthreads();
        if (t + 2 < ntile) load_stage(t + 2, sm + ((t + 2) % 3) * STAGEB);
        asm volatile("cp.async.commit_group;");

        char* Ab = sm + (t % 3) * STAGEB;
        char* Bb = Ab + ABUFB;
        #pragma unroll
        for (int s16 = 0; s16 < 2; s16++) {
            uint32_t a[4][4];
            #pragma unroll
            for (int fm = 0; fm < 4; fm++) {
                int r = wm + fm * 16 + (lane & 15);
                uint32_t addr = s2u(Ab + r * APITCHB + (s16 * 2 + (lane >> 4)) * 16);
                ldsm_x4(a[fm], addr);
            }
            uint32_t b[8][2];
            #pragma unroll
            for (int fnp = 0; fnp < 4; fnp++) {
                int k = s16 * 16 + (lane & 7) + ((lane >> 3) & 1) * 8;
                int u = ((wn + fnp * 16) >> 3) + (lane >> 4);
                uint32_t addr = s2u(Bb + k * 512 + ((u ^ (k & 7)) * 16));
                uint32_t r4[4];
                ldsm_x4_t(r4, addr);
                b[2 * fnp][0] = r4[0]; b[2 * fnp][1] = r4[1];
                b[2 * fnp + 1][0] = r4[2]; b[2 * fnp + 1][1] = r4[3];
            }
            #pragma unroll
            for (int fm = 0; fm < 4; fm++)
                #pragma unroll
                for (int fn = 0; fn < 8; fn++)
                    mma_f16(c[fm][fn], a[fm], b[fn][0], b[fn][1]);
        }
        __syncthreads();
    }
}

// ---------------------------------------------------------------- QKV GEMM (fp16)
__global__ __launch_bounds__(256, 1) void k_qkv_tc(
    int l, const float* __restrict__ bq, const float* __restrict__ bk_, const float* __restrict__ bv)
{
    extern __shared__ char smbuf[];
    const __half* Bg; const float* bias; __half* C;
    if (blockIdx.z == 0)      { Bg = g_Wqh + (size_t)l * H * H; bias = bq;  C = g_Qh; }
    else if (blockIdx.z == 1) { Bg = g_Wkh + (size_t)l * H * H; bias = bk_; C = g_Kh; }
    else                      { Bg = g_Wvh + (size_t)l * H * H; bias = bv;  C = g_Vh; }
    int m0 = blockIdx.y * 128, n0 = blockIdx.x * 256;
    const __half* Arow = g_H1h + (size_t)(m0 + (threadIdx.x >> 1)) * H;
    float c[4][8][4] = {};
    gemm_mainloop_h(Arow, 1, Bg, H, H, n0, c, smbuf);

    int lane = threadIdx.x & 31, warp = threadIdx.x >> 5;
    int grp = lane >> 2, qid = lane & 3;
    int wm = (warp & 1) * 64, wn = (warp >> 1) * 64;
    #pragma unroll
    for (int fn = 0; fn < 8; fn++) {
        int col = n0 + wn + fn * 8 + qid * 2;
        float bx = bias[col], by = bias[col + 1];
        #pragma unroll
        for (int fm = 0; fm < 4; fm++) {
            int m = m0 + wm + fm * 16 + grp;
            *(__half2*)&C[(size_t)m * H + col]       = __floats2half2_rn(c[fm][fn][0] + bx, c[fm][fn][1] + by);
            *(__half2*)&C[(size_t)(m + 8) * H + col] = __floats2half2_rn(c[fm][fn][2] + bx, c[fm][fn][3] + by);
        }
    }
}

// ---------------------------------------------------------------- FFN GEMM1 (gather + gelu, fp16)
__device__ __forceinline__ float gelu_f(float v) {
    return 0.5f * v * (1.0f + erff(v * 0.70710678118654752f));
}

__global__ __launch_bounds__(256, 1) void k_ffn1_tc(int l, const float* __restrict__ b1l)
{
    extern __shared__ char smbuf[];
    int e = blockIdx.z;
    int cnt = g_cnt[e];
    int m0 = blockIdx.y * 128;
    if (m0 >= cnt) return;
    int off = g_off[e];
    int n0 = blockIdx.x * 256;
    const __half* Bg = g_W1h + ((size_t)l * NE + e) * H * FF;
    const float* bias = b1l + (size_t)e * FF;

    int s = m0 + (threadIdx.x >> 1);
    int valid = (s < cnt);
    const __half* Arow = g_H1h + (size_t)(valid ? g_perm[off + s] : 0) * H;
    float c[4][8][4] = {};
    gemm_mainloop_h(Arow, valid, Bg, FF, H, n0, c, smbuf);

    int lane = threadIdx.x & 31, warp = threadIdx.x >> 5;
    int grp = lane >> 2, qid = lane & 3;
    int wm = (warp & 1) * 64, wn = (warp >> 1) * 64;
    #pragma unroll
    for (int fn = 0; fn < 8; fn++) {
        int col = n0 + wn + fn * 8 + qid * 2;
        float bx = bias[col], by = bias[col + 1];
        #pragma unroll
        for (int fm = 0; fm < 4; fm++) {
            int gm = m0 + wm + fm * 16 + grp;
            if (gm < cnt) {
                size_t r = (size_t)(off + gm) * FF + col;
                *(__half2*)&g_midh[r] = __floats2half2_rn(gelu_f(c[fm][fn][0] + bx), gelu_f(c[fm][fn][1] + by));
            }
            if (gm + 8 < cnt) {
                size_t r = (size_t)(off + gm + 8) * FF + col;
                *(__half2*)&g_midh[r] = __floats2half2_rn(gelu_f(c[fm][fn][2] + bx), gelu_f(c[fm][fn][3] + by));
            }
        }
    }
}

// ---------------------------------------------------------------- FFN GEMM2 (split-K=4, residual scatter)
constexpr int KSPLIT = 4;
constexpr int KCHUNK = FF / KSPLIT;   // 768

__global__ __launch_bounds__(256, 1) void k_ffn2_tc(int l, const float* __restrict__ b2l,
                                                    float* __restrict__ x)
{
    extern __shared__ char smbuf[];
    int e = blockIdx.z >> 2;
    int ks = blockIdx.z & 3;
    int cnt = g_cnt[e];
    int m0 = blockIdx.y * 128;
    if (m0 >= cnt) return;
    int off = g_off[e];
    int n0 = blockIdx.x * 256;
    int kbase = ks * KCHUNK;
    const __half* Bg = g_W2h + ((size_t)l * NE + e) * FF * H + (size_t)kbase * H;
    const float* bias = b2l + (size_t)e * H;

    int s = m0 + (threadIdx.x >> 1);
    int valid = (s < cnt);
    const __half* Arow = g_midh + (size_t)(off + (valid ? s : m0)) * FF + kbase;
    float c[4][8][4] = {};
    gemm_mainloop_h(Arow, valid, Bg, H, KCHUNK, n0, c, smbuf);

    int lane = threadIdx.x & 31, warp = threadIdx.x >> 5;
    int grp = lane >> 2, qid = lane & 3;
    int wm = (warp & 1) * 64, wn = (warp >> 1) * 64;

    int tok0[4], tok1[4];
    #pragma unroll
    for (int fm = 0; fm < 4; fm++) {
        int gm = m0 + wm + fm * 16 + grp;
        tok0[fm] = (gm < cnt)     ? g_perm[off + gm]     : -1;
        tok1[fm] = (gm + 8 < cnt) ? g_perm[off + gm + 8] : -1;
    }
    #pragma unroll
    for (int fn = 0; fn < 8; fn++) {
        int col = n0 + wn + fn * 8 + qid * 2;
        float bx = (ks == 0) ? bias[col]     : 0.f;
        float by = (ks == 0) ? bias[col + 1] : 0.f;
        #pragma unroll
        for (int fm = 0; fm < 4; fm++) {
            if (tok0[fm] >= 0) {
                float* p = &x[(size_t)tok0[fm] * H + col];
                atomicAdd(p,     c[fm][fn][0] + bx);
                atomicAdd(p + 1, c[fm][fn][1] + by);
            }
            if (tok1[fm] >= 0) {
                float* p = &x[(size_t)tok1[fm] * H + col];
                atomicAdd(p,     c[fm][fn][2] + bx);
                atomicAdd(p + 1, c[fm][fn][3] + by);
            }
        }
    }
}

// ---------------------------------------------------------------- attention (fp16 mma)
// block = (64-row q-tile, head, batch), 128 threads / 4 warps; warp owns 16 q-rows.
// smem halves, pitch 64 (128B/row), 16B-unit XOR swizzle u' = u ^ (r&7):
//   Qsh [64][64] @0 (8KB), Ksh [256][64] @8K (32KB), Vsh [256][64] @40K (32KB)
//   Psh [64][256] overlays @0 (32KB, pitch 512B, swizzle u ^ (r&7))
constexpr int ATTN_SMEM = 73728;

__global__ __launch_bounds__(128, 2) void k_attn_tc(float* __restrict__ x) {
    extern __shared__ char smc[];
    char* Qsh = smc;
    char* Ksh = smc + 8192;
    char* Vsh = smc + 40960;
    char* Psh = smc;
    int qt = blockIdx.x, hd = blockIdx.y, b = blockIdx.z;
    int tid = threadIdx.x;
    int lane = tid & 31, warp = tid >> 5;
    int grp = lane >> 2, qid = lane & 3;
    int hoff = hd * HD;
    int m = warp * 16;

    // stage Q/K/V via cp.async
    for (int cc = tid; cc < 64 * 8; cc += 128) {
        int r = cc >> 3, u = cc & 7;
        cp16(Qsh + r * 128 + ((u ^ (r & 7)) * 16),
             g_Qh + (size_t)(b * Sq + qt * 64 + r) * H + hoff + u * 8, 1);
    }
    for (int cc = tid; cc < 256 * 8; cc += 128) {
        int r = cc >> 3, u = cc & 7;
        cp16(Ksh + r * 128 + ((u ^ (r & 7)) * 16),
             g_Kh + (size_t)(b * Sq + r) * H + hoff + u * 8, 1);
        cp16(Vsh + r * 128 + ((u ^ (r & 7)) * 16),
             g_Vh + (size_t)(b * Sq + r) * H + hoff + u * 8, 1);
    }
    asm volatile("cp.async.commit_group;");
    asm volatile("cp.async.wait_group 0;");
    __syncthreads();

    // ---- scores: warp tile 16x256, K=64 (4 k16-steps)
    float c[32][4];
    #pragma unroll
    for (int fn = 0; fn < 32; fn++)
        #pragma unroll
        for (int j = 0; j < 4; j++) c[fn][j] = 0.f;

    #pragma unroll
    for (int s = 0; s < 4; s++) {
        uint32_t a[4];
        {
            int r = m + (lane & 15);
            ldsm_x4(a, s2u(Qsh + r * 128 + (((s * 2 + (lane >> 4)) ^ (r & 7)) * 16)));
        }
        #pragma unroll
        for (int nb = 0; nb < 16; nb++) {
            int r = nb * 16 + (lane & 15);
            uint32_t bb[4];
            ldsm_x4(bb, s2u(Ksh + r * 128 + (((s * 2 + (lane >> 4)) ^ (r & 7)) * 16)));
            mma_f16(c[2 * nb],     a, bb[0], bb[2]);
            mma_f16(c[2 * nb + 1], a, bb[1], bb[3]);
        }
    }
    __syncthreads();   // all warps done reading Q/K before P overwrite

    // ---- softmax (row r0 = m+grp: c[..][0,1]; row r1 = r0+8: c[..][2,3]); quad = full row
    float mx0 = -1e30f, mx1 = -1e30f;
    #pragma unroll
    for (int fn = 0; fn < 32; fn++) {
        mx0 = fmaxf(mx0, fmaxf(c[fn][0], c[fn][1]));
        mx1 = fmaxf(mx1, fmaxf(c[fn][2], c[fn][3]));
    }
    #pragma unroll
    for (int o = 1; o <= 2; o <<= 1) {
        mx0 = fmaxf(mx0, __shfl_xor_sync(0xffffffffu, mx0, o));
        mx1 = fmaxf(mx1, __shfl_xor_sync(0xffffffffu, mx1, o));
    }
    float s0 = 0.f, s1 = 0.f;
    #pragma unroll
    for (int fn = 0; fn < 32; fn++) {
        c[fn][0] = __expf(c[fn][0] - mx0); s0 += c[fn][0];
        c[fn][1] = __expf(c[fn][1] - mx0); s0 += c[fn][1];
        c[fn][2] = __expf(c[fn][2] - mx1); s1 += c[fn][2];
        c[fn][3] = __expf(c[fn][3] - mx1); s1 += c[fn][3];
    }
    #pragma unroll
    for (int o = 1; o <= 2; o <<= 1) {
        s0 += __shfl_xor_sync(0xffffffffu, s0, o);
        s1 += __shfl_xor_sync(0xffffffffu, s1, o);
    }
    float inv0 = 1.f / s0, inv1 = 1.f / s1;
    // store P as fp16 (pitch 512B, swizzled); warp writes only its own 16 rows
    #pragma unroll
    for (int fn = 0; fn < 32; fn++) {
        int r0 = m + grp, r1 = r0 + 8;
        int u0 = fn ^ (r0 & 7), u1 = fn ^ (r1 & 7);
        *(__half2*)(Psh + r0 * 512 + u0 * 16 + qid * 4) = __floats2half2_rn(c[fn][0] * inv0, c[fn][1] * inv0);
        *(__half2*)(Psh + r1 * 512 + u1 * 16 + qid * 4) = __floats2half2_rn(c[fn][2] * inv1, c[fn][3] * inv1);
    }
    __syncwarp();

    // ---- PV: warp tile 16x64, K=256 (16 k16-steps)
    float c2[8][4];
    #pragma unroll
    for (int fn = 0; fn < 8; fn++)
        #pragma unroll
        for (int j = 0; j < 4; j++) c2[fn][j] = 0.f;

    #pragma unroll 4
    for (int s = 0; s < 16; s++) {
        uint32_t a[4];
        {
            int r = m + (lane & 15);
            int u = s * 2 + (lane >> 4);
            ldsm_x4(a, s2u(Psh + r * 512 + ((u ^ (r & 7)) * 16)));
        }
        #pragma unroll
        for (int nb = 0; nb < 4; nb++) {
            int k = s * 16 + (lane & 7) + ((lane >> 3) & 1) * 8;
            int u = nb * 2 + (lane >> 4);
            uint32_t r4[4];
            ldsm_x4_t(r4, s2u(Vsh + k * 128 + ((u ^ (k & 7)) * 16)));
            mma_f16(c2[2 * nb],     a, r4[0], r4[1]);
            mma_f16(c2[2 * nb + 1], a, r4[2], r4[3]);
        }
    }

    // ---- epilogue: x += ctx
    #pragma unroll
    for (int fn = 0; fn < 8; fn++) {
        int col = hoff + fn * 8 + qid * 2;
        size_t r0 = (size_t)(b * Sq + qt * 64 + m + grp) * H + col;
        size_t r1 = r0 + (size_t)8 * H;
        float2 v0 = *(float2*)&x[r0];
        v0.x += c2[fn][0]; v0.y += c2[fn][1];
        *(float2*)&x[r0] = v0;
        float2 v1 = *(float2*)&x[r1];
        v1.x += c2[fn][2]; v1.y += c2[fn][3];
        *(float2*)&x[r1] = v1;
    }
}

// ---------------------------------------------------------------- launch
extern "C" void kernel_launch(void* const* d_in, const int* in_sizes, int n_in,
                              void* d_out, int out_size) {
    (void)in_sizes; (void)n_in; (void)out_size;
    const float* x_in  = (const float*)d_in[0];
    const int*   ntp   = (const int*)d_in[2];
    const float* Wq    = (const float*)d_in[3];
    const float* bq    = (const float*)d_in[4];
    const float* Wk    = (const float*)d_in[5];
    const float* bk    = (const float*)d_in[6];
    const float* Wv    = (const float*)d_in[7];
    const float* bv    = (const float*)d_in[8];
    const float* ln1w  = (const float*)d_in[9];
    const float* ln1b  = (const float*)d_in[10];
    const float* ln2w  = (const float*)d_in[11];
    const float* ln2b  = (const float*)d_in[12];
    const float* W1    = (const float*)d_in[13];
    const float* b1    = (const float*)d_in[14];
    const float* W2    = (const float*)d_in[15];
    const float* b2    = (const float*)d_in[16];
    float* x = (float*)d_out;

    cudaFuncSetAttribute(k_attn_tc, cudaFuncAttributeMaxDynamicSharedMemorySize, ATTN_SMEM);
    cudaFuncSetAttribute(k_qkv_tc,  cudaFuncAttributeMaxDynamicSharedMemorySize, GEMM_SMEM);
    cudaFuncSetAttribute(k_ffn1_tc, cudaFuncAttributeMaxDynamicSharedMemorySize, GEMM_SMEM);
    cudaFuncSetAttribute(k_ffn2_tc, cudaFuncAttributeMaxDynamicSharedMemorySize, GEMM_SMEM);

    // weight conversion (fp32 -> fp16)
    {
        __half* dWq; cudaGetSymbolAddress((void**)&dWq, g_Wqh);
        __half* dWk; cudaGetSymbolAddress((void**)&dWk, g_Wkh);
        __half* dWv; cudaGetSymbolAddress((void**)&dWv, g_Wvh);
        __half* dW1; cudaGetSymbolAddress((void**)&dW1, g_W1h);
        __half* dW2; cudaGetSymbolAddress((void**)&dW2, g_W2h);
        int nqkv = Lr * H * H;
        int nff  = Lr * NE * H * FF;
        k_f2h<<<(nqkv / 4 + 255) / 256, 256>>>(Wq, dWq, nqkv);
        k_f2h<<<(nqkv / 4 + 255) / 256, 256>>>(Wk, dWk, nqkv);
        k_f2h<<<(nqkv / 4 + 255) / 256, 256>>>(Wv, dWv, nqkv);
        k_f2h<<<(nff / 4 + 255) / 256, 256>>>(W1, dW1, nff);
        k_f2h<<<(nff / 4 + 255) / 256, 256>>>(W2, dW2, nff);
    }

    k_add_pe<<<(T * H + 255) / 256, 256>>>(x_in, x);
    k_route<<<1, 256>>>(ntp);

    for (int l = 0; l < Lr; l++) {
        k_ln<<<T, 256>>>(x, ln1w + l * H, ln1b + l * H);
        k_qkv_tc<<<dim3(H / 256, T / 128, 3), 256, GEMM_SMEM>>>(
            l, bq + l * H, bk + l * H, bv + l * H);
        k_attn_tc<<<dim3(Sq / 64, NH, Bz), 128, ATTN_SMEM>>>(x);
        k_ln<<<T, 256>>>(x, ln2w + l * H, ln2b + l * H);
        k_ffn1_tc<<<dim3(FF / 256, T / 128, NE), 256, GEMM_SMEM>>>(
            l, b1 + (size_t)l * NE * FF);
        k_ffn2_tc<<<dim3(H / 256, T / 128, NE * KSPLIT), 256, GEMM_SMEM>>>(
            l, b2 + (size_t)l * NE * H, x);
    }
}

// round 11
// speedup vs baseline: 5.9456x; 1.1484x over previous
#include <cuda_runtime.h>
#include <cuda_fp16.h>
#include <math.h>
#include <stdint.h>

// Problem constants
constexpr int Bz = 8, Sq = 256, H = 768, Lr = 2, NE = 4, FF = 3072;
constexpr int NH = 12, HD = 64;
constexpr int T = Bz * Sq;
constexpr float EPS = 1e-5f;

// fp16 scratch
__device__ __half g_H1h[T * H];
__device__ __half g_Qh[T * H];
__device__ __half g_Kh[T * H];
__device__ __half g_Vh[T * H];
__device__ __half g_midh[(size_t)T * FF];
__device__ __half g_Wqh[Lr * H * H];
__device__ __half g_Wkh[Lr * H * H];
__device__ __half g_Wvh[Lr * H * H];
__device__ __half g_W1h[(size_t)Lr * NE * H * FF];
__device__ __half g_W2h[(size_t)Lr * NE * FF * H];
__device__ int   g_perm[T];
__device__ int   g_rank[T];
__device__ int   g_cnt[NE];
__device__ int   g_off[NE];

// GEMM smem geometry (bytes). Stage = BK=32 k-slice. Block tile 128x128, 3 stages.
// A: 128 rows x 32 halves (64B data), pitch 80B.
// B: 32 k-rows x 128 halves (256B row), 16B-unit XOR swizzle u' = u ^ (k&7).
constexpr int APITCHB = 80;
constexpr int ABUFB = 128 * APITCHB;     // 10240
constexpr int BBUFB = 32 * 256;          // 8192
constexpr int STAGEB = ABUFB + BBUFB;    // 18432
constexpr int GEMM_SMEM = 3 * STAGEB;    // 55296

// ---------------------------------------------------------------- fp32 -> fp16 convert
__global__ void k_f2h(const float* __restrict__ in, __half* __restrict__ out, int n) {
    int i = (blockIdx.x * blockDim.x + threadIdx.x) * 4;
    if (i >= n) return;
    float4 v = *(const float4*)(in + i);
    *(__half2*)(out + i)     = __floats2half2_rn(v.x, v.y);
    *(__half2*)(out + i + 2) = __floats2half2_rn(v.z, v.w);
}

// ---------------------------------------------------------------- PE add
__global__ void k_add_pe(const float* __restrict__ xin, float* __restrict__ x) {
    int idx = blockIdx.x * blockDim.x + threadIdx.x;
    if (idx >= T * H) return;
    int d = idx % H;
    int s = (idx / H) % Sq;
    int i2 = d & ~1;
    float div = expf(-(float)i2 * (9.210340371976184f / (float)H));
    float ang = (float)s * div;
    float pe = (d & 1) ? cosf(ang) : sinf(ang);
    x[idx] = xin[idx] + pe;
}

// ---------------------------------------------------------------- routing
__global__ void k_route(const int* __restrict__ ntp) {
    __shared__ int scnt[NE];
    __shared__ int soff[NE];
    int tid = threadIdx.x;
    if (tid < NE) scnt[tid] = 0;
    __syncthreads();
    for (int t = tid; t < T; t += blockDim.x) {
        int e = ntp[t];
        g_rank[t] = atomicAdd(&scnt[e], 1);
    }
    __syncthreads();
    if (tid == 0) {
        int a = 0;
        for (int e = 0; e < NE; e++) {
            soff[e] = a; g_off[e] = a; g_cnt[e] = scnt[e]; a += scnt[e];
        }
    }
    __syncthreads();
    for (int t = tid; t < T; t += blockDim.x) {
        int e = ntp[t];
        g_perm[soff[e] + g_rank[t]] = t;
    }
}

// ---------------------------------------------------------------- layernorm (fp16 out)
__device__ __forceinline__ float block_sum_768(float v) {
    __shared__ float red[8];
    int tid = threadIdx.x;
    #pragma unroll
    for (int o = 16; o; o >>= 1) v += __shfl_xor_sync(0xffffffffu, v, o);
    if ((tid & 31) == 0) red[tid >> 5] = v;
    __syncthreads();
    float t = 0.f;
    if (tid < 32) {
        t = (tid < 8) ? red[tid] : 0.f;
        #pragma unroll
        for (int o = 4; o; o >>= 1) t += __shfl_xor_sync(0xffffffffu, t, o);
        if (tid == 0) red[0] = t;
    }
    __syncthreads();
    float r = red[0];
    __syncthreads();
    return r;
}

__global__ __launch_bounds__(256) void k_ln(const float* __restrict__ x,
                                            const float* __restrict__ w,
                                            const float* __restrict__ b) {
    int row = blockIdx.x;
    int tid = threadIdx.x;
    const float* xr = x + (size_t)row * H;
    float v0 = xr[tid], v1 = xr[tid + 256], v2 = xr[tid + 512];
    float mu = block_sum_768(v0 + v1 + v2) * (1.0f / H);
    float d0 = v0 - mu, d1 = v1 - mu, d2 = v2 - mu;
    float var = block_sum_768(d0 * d0 + d1 * d1 + d2 * d2) * (1.0f / H);
    float rstd = rsqrtf(var + EPS);
    __half* orow = g_H1h + (size_t)row * H;
    orow[tid]       = __float2half(d0 * rstd * w[tid]       + b[tid]);
    orow[tid + 256] = __float2half(d1 * rstd * w[tid + 256] + b[tid + 256]);
    orow[tid + 512] = __float2half(d2 * rstd * w[tid + 512] + b[tid + 512]);
}

// ---------------------------------------------------------------- mma / ldsm helpers
__device__ __forceinline__ uint32_t s2u(const void* p) {
    return (uint32_t)__cvta_generic_to_shared(p);
}

__device__ __forceinline__ void ldsm_x4(uint32_t (&r)[4], uint32_t addr) {
    asm volatile("ldmatrix.sync.aligned.m8n8.x4.shared.b16 {%0,%1,%2,%3}, [%4];"
        : "=r"(r[0]), "=r"(r[1]), "=r"(r[2]), "=r"(r[3]) : "r"(addr));
}

__device__ __forceinline__ void ldsm_x4_t(uint32_t (&r)[4], uint32_t addr) {
    asm volatile("ldmatrix.sync.aligned.m8n8.x4.trans.shared.b16 {%0,%1,%2,%3}, [%4];"
        : "=r"(r[0]), "=r"(r[1]), "=r"(r[2]), "=r"(r[3]) : "r"(addr));
}

__device__ __forceinline__ void mma_f16(float (&c)[4], const uint32_t (&a)[4], uint32_t b0, uint32_t b1) {
    asm volatile(
        "mma.sync.aligned.m16n8k16.row.col.f32.f16.f16.f32 "
        "{%0,%1,%2,%3},{%4,%5,%6,%7},{%8,%9},{%0,%1,%2,%3};"
        : "+f"(c[0]), "+f"(c[1]), "+f"(c[2]), "+f"(c[3])
        : "r"(a[0]), "r"(a[1]), "r"(a[2]), "r"(a[3]), "r"(b0), "r"(b1));
}

__device__ __forceinline__ void cp16(void* s, const void* g, int pred) {
    uint32_t sa = s2u(s);
    asm volatile(
        "{\n\t.reg .pred p;\n\t"
        "setp.ne.b32 p, %2, 0;\n\t"
        ".reg .b32 sz;\n\t"
        "selp.b32 sz, 16, 0, p;\n\t"
        "cp.async.ca.shared.global [%0], [%1], 16, sz;\n\t}"
        :: "r"(sa), "l"(g), "r"(pred));
}

// ---------------------------------------------------------------- fp16 GEMM core
// Block tile 128x128, 256 thr / 8 warps (4x2), warp tile 32x64, BK=32, 3-stage cp.async,
// single __syncthreads per k-iteration. 2 CTAs/SM.
__device__ __forceinline__ void gemm_mainloop_h(
    const __half* __restrict__ Arow, int avalid,
    const __half* __restrict__ Bg, int ldB, int Kdim, int n0,
    float (&c)[2][8][4], char* sm)
{
    int tid = threadIdx.x;
    int lane = tid & 31, warp = tid >> 5;
    int wm = (warp & 3) * 32, wn = (warp >> 2) * 64;

    int arow = tid >> 1;
    int ah0 = (tid & 1) * 2;
    int ntile = Kdim / 32;

    auto load_stage = [&](int t, char* dst) {
        int kt = t * 32;
        char* As = dst;
        char* Bs = dst + ABUFB;
        const __half* ag = Arow + kt + ah0 * 8;
        cp16(As + arow * APITCHB + ah0 * 16,       ag,     avalid);
        cp16(As + arow * APITCHB + (ah0 + 1) * 16, ag + 8, avalid);
        #pragma unroll
        for (int j = 0; j < 2; j++) {
            int cc = tid * 2 + j;
            int k = cc >> 4, u = cc & 15;
            cp16(Bs + k * 256 + ((u ^ (k & 7)) * 16),
                 Bg + (size_t)(kt + k) * ldB + n0 + u * 8, 1);
        }
    };

    load_stage(0, sm);
    asm volatile("cp.async.commit_group;");
    if (ntile > 1) load_stage(1, sm + STAGEB);
    asm volatile("cp.async.commit_group;");

    for (int t = 0; t < ntile; t++) {
        asm volatile("cp.async.wait_group 1;");
        __syncthreads();
        if (t + 2 < ntile) load_stage(t + 2, sm + ((t + 2) % 3) * STAGEB);
        asm volatile("cp.async.commit_group;");

        char* Ab = sm + (t % 3) * STAGEB;
        char* Bb = Ab + ABUFB;
        #pragma unroll
        for (int s16 = 0; s16 < 2; s16++) {
            uint32_t a[2][4];
            #pragma unroll
            for (int fm = 0; fm < 2; fm++) {
                int r = wm + fm * 16 + (lane & 15);
                uint32_t addr = s2u(Ab + r * APITCHB + (s16 * 2 + (lane >> 4)) * 16);
                ldsm_x4(a[fm], addr);
            }
            uint32_t b[8][2];
            #pragma unroll
            for (int fnp = 0; fnp < 4; fnp++) {
                int k = s16 * 16 + (lane & 7) + ((lane >> 3) & 1) * 8;
                int u = ((wn + fnp * 16) >> 3) + (lane >> 4);
                uint32_t addr = s2u(Bb + k * 256 + ((u ^ (k & 7)) * 16));
                uint32_t r4[4];
                ldsm_x4_t(r4, addr);
                b[2 * fnp][0] = r4[0]; b[2 * fnp][1] = r4[1];
                b[2 * fnp + 1][0] = r4[2]; b[2 * fnp + 1][1] = r4[3];
            }
            #pragma unroll
            for (int fm = 0; fm < 2; fm++)
                #pragma unroll
                for (int fn = 0; fn < 8; fn++)
                    mma_f16(c[fm][fn], a[fm], b[fn][0], b[fn][1]);
        }
        __syncthreads();
    }
    asm volatile("cp.async.wait_group 0;");
}

// ---------------------------------------------------------------- QKV GEMM (fp16)
__global__ __launch_bounds__(256, 2) void k_qkv_tc(
    int l, const float* __restrict__ bq, const float* __restrict__ bk_, const float* __restrict__ bv)
{
    extern __shared__ char smbuf[];
    const __half* Bg; const float* bias; __half* C;
    if (blockIdx.z == 0)      { Bg = g_Wqh + (size_t)l * H * H; bias = bq;  C = g_Qh; }
    else if (blockIdx.z == 1) { Bg = g_Wkh + (size_t)l * H * H; bias = bk_; C = g_Kh; }
    else                      { Bg = g_Wvh + (size_t)l * H * H; bias = bv;  C = g_Vh; }
    int m0 = blockIdx.y * 128, n0 = blockIdx.x * 128;
    const __half* Arow = g_H1h + (size_t)(m0 + (threadIdx.x >> 1)) * H;
    float c[2][8][4] = {};
    gemm_mainloop_h(Arow, 1, Bg, H, H, n0, c, smbuf);

    int lane = threadIdx.x & 31, warp = threadIdx.x >> 5;
    int grp = lane >> 2, qid = lane & 3;
    int wm = (warp & 3) * 32, wn = (warp >> 2) * 64;
    #pragma unroll
    for (int fn = 0; fn < 8; fn++) {
        int col = n0 + wn + fn * 8 + qid * 2;
        float bx = bias[col], by = bias[col + 1];
        #pragma unroll
        for (int fm = 0; fm < 2; fm++) {
            int m = m0 + wm + fm * 16 + grp;
            *(__half2*)&C[(size_t)m * H + col]       = __floats2half2_rn(c[fm][fn][0] + bx, c[fm][fn][1] + by);
            *(__half2*)&C[(size_t)(m + 8) * H + col] = __floats2half2_rn(c[fm][fn][2] + bx, c[fm][fn][3] + by);
        }
    }
}

// ---------------------------------------------------------------- FFN GEMM1 (gather + gelu, fp16)
__device__ __forceinline__ float gelu_f(float v) {
    return 0.5f * v * (1.0f + erff(v * 0.70710678118654752f));
}

__global__ __launch_bounds__(256, 2) void k_ffn1_tc(int l, const float* __restrict__ b1l)
{
    extern __shared__ char smbuf[];
    int e = blockIdx.z;
    int cnt = g_cnt[e];
    int m0 = blockIdx.y * 128;
    if (m0 >= cnt) return;
    int off = g_off[e];
    int n0 = blockIdx.x * 128;
    const __half* Bg = g_W1h + ((size_t)l * NE + e) * H * FF;
    const float* bias = b1l + (size_t)e * FF;

    int s = m0 + (threadIdx.x >> 1);
    int valid = (s < cnt);
    const __half* Arow = g_H1h + (size_t)(valid ? g_perm[off + s] : 0) * H;
    float c[2][8][4] = {};
    gemm_mainloop_h(Arow, valid, Bg, FF, H, n0, c, smbuf);

    int lane = threadIdx.x & 31, warp = threadIdx.x >> 5;
    int grp = lane >> 2, qid = lane & 3;
    int wm = (warp & 3) * 32, wn = (warp >> 2) * 64;
    #pragma unroll
    for (int fn = 0; fn < 8; fn++) {
        int col = n0 + wn + fn * 8 + qid * 2;
        float bx = bias[col], by = bias[col + 1];
        #pragma unroll
        for (int fm = 0; fm < 2; fm++) {
            int gm = m0 + wm + fm * 16 + grp;
            if (gm < cnt) {
                size_t r = (size_t)(off + gm) * FF + col;
                *(__half2*)&g_midh[r] = __floats2half2_rn(gelu_f(c[fm][fn][0] + bx), gelu_f(c[fm][fn][1] + by));
            }
            if (gm + 8 < cnt) {
                size_t r = (size_t)(off + gm + 8) * FF + col;
                *(__half2*)&g_midh[r] = __floats2half2_rn(gelu_f(c[fm][fn][2] + bx), gelu_f(c[fm][fn][3] + by));
            }
        }
    }
}

// ---------------------------------------------------------------- FFN GEMM2 (split-K=2, residual scatter)
constexpr int KSPLIT = 2;
constexpr int KCHUNK = FF / KSPLIT;   // 1536

__global__ __launch_bounds__(256, 2) void k_ffn2_tc(int l, const float* __restrict__ b2l,
                                                    float* __restrict__ x)
{
    extern __shared__ char smbuf[];
    int e = blockIdx.z >> 1;
    int ks = blockIdx.z & 1;
    int cnt = g_cnt[e];
    int m0 = blockIdx.y * 128;
    if (m0 >= cnt) return;
    int off = g_off[e];
    int n0 = blockIdx.x * 128;
    int kbase = ks * KCHUNK;
    const __half* Bg = g_W2h + ((size_t)l * NE + e) * FF * H + (size_t)kbase * H;
    const float* bias = b2l + (size_t)e * H;

    int s = m0 + (threadIdx.x >> 1);
    int valid = (s < cnt);
    const __half* Arow = g_midh + (size_t)(off + (valid ? s : m0)) * FF + kbase;
    float c[2][8][4] = {};
    gemm_mainloop_h(Arow, valid, Bg, H, KCHUNK, n0, c, smbuf);

    int lane = threadIdx.x & 31, warp = threadIdx.x >> 5;
    int grp = lane >> 2, qid = lane & 3;
    int wm = (warp & 3) * 32, wn = (warp >> 2) * 64;

    int tok0[2], tok1[2];
    #pragma unroll
    for (int fm = 0; fm < 2; fm++) {
        int gm = m0 + wm + fm * 16 + grp;
        tok0[fm] = (gm < cnt)     ? g_perm[off + gm]     : -1;
        tok1[fm] = (gm + 8 < cnt) ? g_perm[off + gm + 8] : -1;
    }
    #pragma unroll
    for (int fn = 0; fn < 8; fn++) {
        int col = n0 + wn + fn * 8 + qid * 2;
        float bx = (ks == 0) ? bias[col]     : 0.f;
        float by = (ks == 0) ? bias[col + 1] : 0.f;
        #pragma unroll
        for (int fm = 0; fm < 2; fm++) {
            if (tok0[fm] >= 0) {
                float* p = &x[(size_t)tok0[fm] * H + col];
                atomicAdd(p,     c[fm][fn][0] + bx);
                atomicAdd(p + 1, c[fm][fn][1] + by);
            }
            if (tok1[fm] >= 0) {
                float* p = &x[(size_t)tok1[fm] * H + col];
                atomicAdd(p,     c[fm][fn][2] + bx);
                atomicAdd(p + 1, c[fm][fn][3] + by);
            }
        }
    }
}

// ---------------------------------------------------------------- attention (fp16 mma, unchanged from R7)
constexpr int ATTN_SMEM = 73728;

__global__ __launch_bounds__(128, 2) void k_attn_tc(float* __restrict__ x) {
    extern __shared__ char smc[];
    char* Qsh = smc;
    char* Ksh = smc + 8192;
    char* Vsh = smc + 40960;
    char* Psh = smc;
    int qt = blockIdx.x, hd = blockIdx.y, b = blockIdx.z;
    int tid = threadIdx.x;
    int lane = tid & 31, warp = tid >> 5;
    int grp = lane >> 2, qid = lane & 3;
    int hoff = hd * HD;
    int m = warp * 16;

    for (int cc = tid; cc < 64 * 8; cc += 128) {
        int r = cc >> 3, u = cc & 7;
        cp16(Qsh + r * 128 + ((u ^ (r & 7)) * 16),
             g_Qh + (size_t)(b * Sq + qt * 64 + r) * H + hoff + u * 8, 1);
    }
    for (int cc = tid; cc < 256 * 8; cc += 128) {
        int r = cc >> 3, u = cc & 7;
        cp16(Ksh + r * 128 + ((u ^ (r & 7)) * 16),
             g_Kh + (size_t)(b * Sq + r) * H + hoff + u * 8, 1);
        cp16(Vsh + r * 128 + ((u ^ (r & 7)) * 16),
             g_Vh + (size_t)(b * Sq + r) * H + hoff + u * 8, 1);
    }
    asm volatile("cp.async.commit_group;");
    asm volatile("cp.async.wait_group 0;");
    __syncthreads();

    float c[32][4];
    #pragma unroll
    for (int fn = 0; fn < 32; fn++)
        #pragma unroll
        for (int j = 0; j < 4; j++) c[fn][j] = 0.f;

    #pragma unroll
    for (int s = 0; s < 4; s++) {
        uint32_t a[4];
        {
            int r = m + (lane & 15);
            ldsm_x4(a, s2u(Qsh + r * 128 + (((s * 2 + (lane >> 4)) ^ (r & 7)) * 16)));
        }
        #pragma unroll
        for (int nb = 0; nb < 16; nb++) {
            int r = nb * 16 + (lane & 15);
            uint32_t bb[4];
            ldsm_x4(bb, s2u(Ksh + r * 128 + (((s * 2 + (lane >> 4)) ^ (r & 7)) * 16)));
            mma_f16(c[2 * nb],     a, bb[0], bb[2]);
            mma_f16(c[2 * nb + 1], a, bb[1], bb[3]);
        }
    }
    __syncthreads();

    float mx0 = -1e30f, mx1 = -1e30f;
    #pragma unroll
    for (int fn = 0; fn < 32; fn++) {
        mx0 = fmaxf(mx0, fmaxf(c[fn][0], c[fn][1]));
        mx1 = fmaxf(mx1, fmaxf(c[fn][2], c[fn][3]));
    }
    #pragma unroll
    for (int o = 1; o <= 2; o <<= 1) {
        mx0 = fmaxf(mx0, __shfl_xor_sync(0xffffffffu, mx0, o));
        mx1 = fmaxf(mx1, __shfl_xor_sync(0xffffffffu, mx1, o));
    }
    float s0 = 0.f, s1 = 0.f;
    #pragma unroll
    for (int fn = 0; fn < 32; fn++) {
        c[fn][0] = __expf(c[fn][0] - mx0); s0 += c[fn][0];
        c[fn][1] = __expf(c[fn][1] - mx0); s0 += c[fn][1];
        c[fn][2] = __expf(c[fn][2] - mx1); s1 += c[fn][2];
        c[fn][3] = __expf(c[fn][3] - mx1); s1 += c[fn][3];
    }
    #pragma unroll
    for (int o = 1; o <= 2; o <<= 1) {
        s0 += __shfl_xor_sync(0xffffffffu, s0, o);
        s1 += __shfl_xor_sync(0xffffffffu, s1, o);
    }
    float inv0 = 1.f / s0, inv1 = 1.f / s1;
    #pragma unroll
    for (int fn = 0; fn < 32; fn++) {
        int r0 = m + grp, r1 = r0 + 8;
        int u0 = fn ^ (r0 & 7), u1 = fn ^ (r1 & 7);
        *(__half2*)(Psh + r0 * 512 + u0 * 16 + qid * 4) = __floats2half2_rn(c[fn][0] * inv0, c[fn][1] * inv0);
        *(__half2*)(Psh + r1 * 512 + u1 * 16 + qid * 4) = __floats2half2_rn(c[fn][2] * inv1, c[fn][3] * inv1);
    }
    __syncwarp();

    float c2[8][4];
    #pragma unroll
    for (int fn = 0; fn < 8; fn++)
        #pragma unroll
        for (int j = 0; j < 4; j++) c2[fn][j] = 0.f;

    #pragma unroll 4
    for (int s = 0; s < 16; s++) {
        uint32_t a[4];
        {
            int r = m + (lane & 15);
            int u = s * 2 + (lane >> 4);
            ldsm_x4(a, s2u(Psh + r * 512 + ((u ^ (r & 7)) * 16)));
        }
        #pragma unroll
        for (int nb = 0; nb < 4; nb++) {
            int k = s * 16 + (lane & 7) + ((lane >> 3) & 1) * 8;
            int u = nb * 2 + (lane >> 4);
            uint32_t r4[4];
            ldsm_x4_t(r4, s2u(Vsh + k * 128 + ((u ^ (k & 7)) * 16)));
            mma_f16(c2[2 * nb],     a, r4[0], r4[1]);
            mma_f16(c2[2 * nb + 1], a, r4[2], r4[3]);
        }
    }

    #pragma unroll
    for (int fn = 0; fn < 8; fn++) {
        int col = hoff + fn * 8 + qid * 2;
        size_t r0 = (size_t)(b * Sq + qt * 64 + m + grp) * H + col;
        size_t r1 = r0 + (size_t)8 * H;
        float2 v0 = *(float2*)&x[r0];
        v0.x += c2[fn][0]; v0.y += c2[fn][1];
        *(float2*)&x[r0] = v0;
        float2 v1 = *(float2*)&x[r1];
        v1.x += c2[fn][2]; v1.y += c2[fn][3];
        *(float2*)&x[r1] = v1;
    }
}

// ---------------------------------------------------------------- launch
extern "C" void kernel_launch(void* const* d_in, const int* in_sizes, int n_in,
                              void* d_out, int out_size) {
    (void)in_sizes; (void)n_in; (void)out_size;
    const float* x_in  = (const float*)d_in[0];
    const int*   ntp   = (const int*)d_in[2];
    const float* Wq    = (const float*)d_in[3];
    const float* bq    = (const float*)d_in[4];
    const float* Wk    = (const float*)d_in[5];
    const float* bk    = (const float*)d_in[6];
    const float* Wv    = (const float*)d_in[7];
    const float* bv    = (const float*)d_in[8];
    const float* ln1w  = (const float*)d_in[9];
    const float* ln1b  = (const float*)d_in[10];
    const float* ln2w  = (const float*)d_in[11];
    const float* ln2b  = (const float*)d_in[12];
    const float* W1    = (const float*)d_in[13];
    const float* b1    = (const float*)d_in[14];
    const float* W2    = (const float*)d_in[15];
    const float* b2    = (const float*)d_in[16];
    float* x = (float*)d_out;

    cudaFuncSetAttribute(k_attn_tc, cudaFuncAttributeMaxDynamicSharedMemorySize, ATTN_SMEM);
    cudaFuncSetAttribute(k_qkv_tc,  cudaFuncAttributeMaxDynamicSharedMemorySize, GEMM_SMEM);
    cudaFuncSetAttribute(k_ffn1_tc, cudaFuncAttributeMaxDynamicSharedMemorySize, GEMM_SMEM);
    cudaFuncSetAttribute(k_ffn2_tc, cudaFuncAttributeMaxDynamicSharedMemorySize, GEMM_SMEM);

    // weight conversion (fp32 -> fp16)
    {
        __half* dWq; cudaGetSymbolAddress((void**)&dWq, g_Wqh);
        __half* dWk; cudaGetSymbolAddress((void**)&dWk, g_Wkh);
        __half* dWv; cudaGetSymbolAddress((void**)&dWv, g_Wvh);
        __half* dW1; cudaGetSymbolAddress((void**)&dW1, g_W1h);
        __half* dW2; cudaGetSymbolAddress((void**)&dW2, g_W2h);
        int nqkv = Lr * H * H;
        int nff  = Lr * NE * H * FF;
        k_f2h<<<(nqkv / 4 + 255) / 256, 256>>>(Wq, dWq, nqkv);
        k_f2h<<<(nqkv / 4 + 255) / 256, 256>>>(Wk, dWk, nqkv);
        k_f2h<<<(nqkv / 4 + 255) / 256, 256>>>(Wv, dWv, nqkv);
        k_f2h<<<(nff / 4 + 255) / 256, 256>>>(W1, dW1, nff);
        k_f2h<<<(nff / 4 + 255) / 256, 256>>>(W2, dW2, nff);
    }

    k_add_pe<<<(T * H + 255) / 256, 256>>>(x_in, x);
    k_route<<<1, 256>>>(ntp);

    for (int l = 0; l < Lr; l++) {
        k_ln<<<T, 256>>>(x, ln1w + l * H, ln1b + l * H);
        k_qkv_tc<<<dim3(H / 128, T / 128, 3), 256, GEMM_SMEM>>>(
            l, bq + l * H, bk + l * H, bv + l * H);
        k_attn_tc<<<dim3(Sq / 64, NH, Bz), 128, ATTN_SMEM>>>(x);
        k_ln<<<T, 256>>>(x, ln2w + l * H, ln2b + l * H);
        k_ffn1_tc<<<dim3(FF / 128, T / 128, NE), 256, GEMM_SMEM>>>(
            l, b1 + (size_t)l * NE * FF);
        k_ffn2_tc<<<dim3(H / 128, T / 128, NE * KSPLIT), 256, GEMM_SMEM>>>(
            l, b2 + (size_t)l * NE * H, x);
    }
}